// round 10
// baseline (speedup 1.0000x reference)
#include <cuda_runtime.h>
#include <cuda_bf16.h>
#include <mma.h>
#include <math.h>

using namespace nvcuda;

#define NN 100000
#define EE 1600000
#define HH 128
#define NPAD (NN + 128)
#define BCAP 64          // bucket capacity per node (Poisson(16); P(>64) ~ 1e-20)

// ---------------- scratch ----------------------------------------------------
__device__ float4 g_bufA4[(size_t)NPAD * HH / 4];
__device__ float4 g_bufB4[(size_t)NPAD * HH / 4];
__device__ float4 g_res4 [(size_t)NPAD * HH / 4];
__device__ float  g_dis [NN];
__device__ float  g_deg [NN];
__device__ float  g_s   [NN];
__device__ int    g_cnt [NN];
__device__ int    g_bsrc[(size_t)NN * BCAP];
__device__ float  g_bew [(size_t)NN * BCAP];

#define SEL_A 0
#define SEL_B 1
#define SEL_R 2
__device__ __forceinline__ float* pick(int sel) {
    return sel == SEL_A ? (float*)g_bufA4
         : (sel == SEL_B ? (float*)g_bufB4 : (float*)g_res4);
}

// ---------------- bucket-CSR build (no scan, single edge pass) ---------------
__global__ void k_init(int n) {
    int i = blockIdx.x * blockDim.x + threadIdx.x;
    if (i < n) { g_deg[i] = 1.0f; g_cnt[i] = 0; }   // deg starts at self-loop weight
}

__global__ void k_fill_bucket(const int* __restrict__ ei,
                              const float* __restrict__ ew, int E) {
    int e = blockIdx.x * blockDim.x + threadIdx.x;
    if (e >= E) return;
    int r = ei[e];
    int c = ei[E + e];
    float w = ew[e];
    atomicAdd(&g_deg[c], w);
    int p = atomicAdd(&g_cnt[c], 1);
    if (p < BCAP) {
        g_bsrc[(size_t)c * BCAP + p] = r;
        g_bew [(size_t)c * BCAP + p] = w;
    }
}

__global__ void k_dis(int n) {
    int i = blockIdx.x * blockDim.x + threadIdx.x;
    if (i < n) g_dis[i] = rsqrtf(g_deg[i]);
}

// ---------------- bf16x3 tensor-core GEMM: C[M,128] = A[M,K] @ B[K,128] ------
#define ASTR 40
#define BSTR 136
__global__ __launch_bounds__(256)
void gemm_bf16x3(const float* __restrict__ A_ext, int selA,
                 const float* __restrict__ B, int selC, int M, int K) {
    const float* A = (selA < 0) ? A_ext : pick(selA);
    float* C = pick(selC);

    __shared__ __nv_bfloat16 AsH[128][ASTR], AsL[128][ASTR];
    __shared__ __nv_bfloat16 BsH[32][BSTR],  BsL[32][BSTR];

    int tid = threadIdx.x;
    int wid = tid >> 5;
    int warpM = wid >> 2;     // 0..1 -> 64 rows
    int warpN = wid & 3;      // 0..3 -> 32 cols
    int row0 = blockIdx.x * 128;

    wmma::fragment<wmma::accumulator, 16, 16, 16, float> acc[4][2];
    #pragma unroll
    for (int i = 0; i < 4; i++)
        #pragma unroll
        for (int j = 0; j < 2; j++) wmma::fill_fragment(acc[i][j], 0.0f);

    int ar = tid >> 3;            // 0..31
    int ac = (tid & 7) * 4;       // 0..28
    int br = tid >> 6;            // 0..3
    int bc = (tid & 63) * 2;      // 0..126

    float4 avr[4];
    float2 bvr[8];

    #pragma unroll
    for (int p = 0; p < 4; p++) {
        int gr = row0 + ar + p * 32;
        avr[p] = make_float4(0.f, 0.f, 0.f, 0.f);
        if (gr < M) avr[p] = *(const float4*)(A + (size_t)gr * K + ac);
    }
    #pragma unroll
    for (int p = 0; p < 8; p++)
        bvr[p] = *(const float2*)(B + (size_t)(br + p * 4) * 128 + bc);

    int ntiles = K >> 5;
    for (int t = 0; t < ntiles; t++) {
        #pragma unroll
        for (int p = 0; p < 4; p++) {
            int r = ar + p * 32;
            float4 v = avr[p];
            __nv_bfloat16 hx = __float2bfloat16(v.x);
            __nv_bfloat16 hy = __float2bfloat16(v.y);
            __nv_bfloat16 hz = __float2bfloat16(v.z);
            __nv_bfloat16 hw = __float2bfloat16(v.w);
            AsH[r][ac+0] = hx; AsL[r][ac+0] = __float2bfloat16(v.x - __bfloat162float(hx));
            AsH[r][ac+1] = hy; AsL[r][ac+1] = __float2bfloat16(v.y - __bfloat162float(hy));
            AsH[r][ac+2] = hz; AsL[r][ac+2] = __float2bfloat16(v.z - __bfloat162float(hz));
            AsH[r][ac+3] = hw; AsL[r][ac+3] = __float2bfloat16(v.w - __bfloat162float(hw));
        }
        #pragma unroll
        for (int p = 0; p < 8; p++) {
            int r = br + p * 4;
            float2 v = bvr[p];
            __nv_bfloat16 hx = __float2bfloat16(v.x);
            __nv_bfloat16 hy = __float2bfloat16(v.y);
            BsH[r][bc+0] = hx; BsL[r][bc+0] = __float2bfloat16(v.x - __bfloat162float(hx));
            BsH[r][bc+1] = hy; BsL[r][bc+1] = __float2bfloat16(v.y - __bfloat162float(hy));
        }
        __syncthreads();

        if (t + 1 < ntiles) {
            int k0 = (t + 1) << 5;
            #pragma unroll
            for (int p = 0; p < 4; p++) {
                int gr = row0 + ar + p * 32;
                avr[p] = make_float4(0.f, 0.f, 0.f, 0.f);
                if (gr < M) avr[p] = *(const float4*)(A + (size_t)gr * K + k0 + ac);
            }
            #pragma unroll
            for (int p = 0; p < 8; p++)
                bvr[p] = *(const float2*)(B + (size_t)(k0 + br + p * 4) * 128 + bc);
        }

        #pragma unroll
        for (int kk = 0; kk < 32; kk += 16) {
            wmma::fragment<wmma::matrix_a, 16, 16, 16, __nv_bfloat16, wmma::row_major> ah[4], al[4];
            wmma::fragment<wmma::matrix_b, 16, 16, 16, __nv_bfloat16, wmma::row_major> bh[2], bl[2];
            #pragma unroll
            for (int i = 0; i < 4; i++) {
                wmma::load_matrix_sync(ah[i], &AsH[warpM * 64 + i * 16][kk], ASTR);
                wmma::load_matrix_sync(al[i], &AsL[warpM * 64 + i * 16][kk], ASTR);
            }
            #pragma unroll
            for (int j = 0; j < 2; j++) {
                wmma::load_matrix_sync(bh[j], &BsH[kk][warpN * 32 + j * 16], BSTR);
                wmma::load_matrix_sync(bl[j], &BsL[kk][warpN * 32 + j * 16], BSTR);
            }
            #pragma unroll
            for (int i = 0; i < 4; i++)
                #pragma unroll
                for (int j = 0; j < 2; j++) {
                    wmma::mma_sync(acc[i][j], al[i], bh[j], acc[i][j]);
                    wmma::mma_sync(acc[i][j], ah[i], bl[j], acc[i][j]);
                    wmma::mma_sync(acc[i][j], ah[i], bh[j], acc[i][j]);
                }
        }
        __syncthreads();
    }

    #pragma unroll
    for (int i = 0; i < 4; i++)
        #pragma unroll
        for (int j = 0; j < 2; j++) {
            float* cp = C + (size_t)(row0 + warpM * 64 + i * 16) * 128 + warpN * 32 + j * 16;
            wmma::store_matrix_sync(cp, acc[i][j], 128, wmma::mem_row_major);
        }
}

// ---------------- fused bucket gather + selfloop + bias (+res) + BN + ReLU ---
// One warp per node. a = dis_c * ( sum_k dis[r_k]*ew_k*h[r_k] + dis_c*h[node] )
__global__ __launch_bounds__(256)
void k_gather_ep(int selH, int selOut,
                 const float* __restrict__ bvec,
                 const float* __restrict__ g, const float* __restrict__ be,
                 const float* __restrict__ m, const float* __restrict__ v,
                 int selRes, const float* __restrict__ w3, int n) {
    int warp = (blockIdx.x * blockDim.x + threadIdx.x) >> 5;
    if (warp >= n) return;
    int lane = threadIdx.x & 31;
    const float* h = pick(selH);

    float dc = g_dis[warp];
    float4 p = *(const float4*)(h + (size_t)warp * 128 + lane * 4);
    float4 a;
    a.x = p.x * dc; a.y = p.y * dc; a.z = p.z * dc; a.w = p.w * dc;

    int cnt = g_cnt[warp];
    if (cnt > BCAP) cnt = BCAP;
    const int*   bs = g_bsrc + (size_t)warp * BCAP;
    const float* bw = g_bew  + (size_t)warp * BCAP;

    int k = 0;
    for (; k + 3 < cnt; k += 4) {
        int   ri[4]; float wi[4];
        #pragma unroll
        for (int u = 0; u < 4; u++) {
            ri[u] = __ldg(&bs[k + u]);
            wi[u] = __ldg(&bw[k + u]) * __ldg(&g_dis[ri[u]]);
        }
        float4 hv[4];
        #pragma unroll
        for (int u = 0; u < 4; u++)
            hv[u] = *(const float4*)(h + (size_t)ri[u] * 128 + lane * 4);
        #pragma unroll
        for (int u = 0; u < 4; u++) {
            a.x += hv[u].x * wi[u];
            a.y += hv[u].y * wi[u];
            a.z += hv[u].z * wi[u];
            a.w += hv[u].w * wi[u];
        }
    }
    for (; k < cnt; k++) {
        int   r0 = __ldg(&bs[k]);
        float w0 = __ldg(&bw[k]) * __ldg(&g_dis[r0]);
        float4 h0 = *(const float4*)(h + (size_t)r0 * 128 + lane * 4);
        a.x += h0.x * w0; a.y += h0.y * w0; a.z += h0.z * w0; a.w += h0.w * w0;
    }

    // scale whole aggregate by dis_c
    a.x *= dc; a.y *= dc; a.z *= dc; a.w *= dc;

    int j4 = lane * 4;
    float4 bv = *(const float4*)(bvec + j4);
    a.x += bv.x; a.y += bv.y; a.z += bv.z; a.w += bv.w;
    if (selRes >= 0) {
        float4 rr = *(const float4*)(pick(selRes) + (size_t)warp * 128 + j4);
        a.x += rr.x; a.y += rr.y; a.z += rr.z; a.w += rr.w;
    }
    float4 gv = *(const float4*)(g + j4);
    float4 vv = *(const float4*)(v + j4);
    float4 mv = *(const float4*)(m + j4);
    float4 bb = *(const float4*)(be + j4);
    float4 o;
    o.x = fmaxf((a.x - mv.x) * (gv.x * rsqrtf(vv.x + 1e-5f)) + bb.x, 0.f);
    o.y = fmaxf((a.y - mv.y) * (gv.y * rsqrtf(vv.y + 1e-5f)) + bb.y, 0.f);
    o.z = fmaxf((a.z - mv.z) * (gv.z * rsqrtf(vv.z + 1e-5f)) + bb.z, 0.f);
    o.w = fmaxf((a.w - mv.w) * (gv.w * rsqrtf(vv.w + 1e-5f)) + bb.w, 0.f);
    *(float4*)(pick(selOut) + (size_t)warp * 128 + j4) = o;

    if (w3) {   // fused GEMV: s = o . w3
        float4 wv = ((const float4*)w3)[lane];
        float s = o.x * wv.x + o.y * wv.y + o.z * wv.z + o.w * wv.w;
        #pragma unroll
        for (int off = 16; off > 0; off >>= 1) s += __shfl_down_sync(0xffffffffu, s, off);
        if (lane == 0) g_s[warp] = s;
    }
}

// ---------------- layer 3: warp-per-node scalar bucket gather ----------------
__global__ __launch_bounds__(256)
void k_out(const float* __restrict__ b3, float* __restrict__ out, int n) {
    int warp = (blockIdx.x * blockDim.x + threadIdx.x) >> 5;
    if (warp >= n) return;
    int lane = threadIdx.x & 31;
    int cnt = g_cnt[warp];
    if (cnt > BCAP) cnt = BCAP;
    const int*   bs = g_bsrc + (size_t)warp * BCAP;
    const float* bw = g_bew  + (size_t)warp * BCAP;
    float acc = 0.0f;
    for (int k = lane; k < cnt; k += 32) {
        int r = __ldg(&bs[k]);
        acc += g_s[r] * __ldg(&bw[k]) * __ldg(&g_dis[r]);
    }
    #pragma unroll
    for (int off = 16; off > 0; off >>= 1) acc += __shfl_down_sync(0xffffffffu, acc, off);
    if (lane == 0) {
        float dc = g_dis[warp];
        out[warp] = b3[0] + dc * (acc + dc * g_s[warp]);
    }
}

// ---------------- launch ----------------------------------------------------
extern "C" void kernel_launch(void* const* d_in, const int* in_sizes, int n_in,
                              void* d_out, int out_size) {
    const float* x    = (const float*)d_in[0];
    const int*   ei   = (const int*)d_in[1];     // int32 (JAX x64 disabled)
    const float* ew   = (const float*)d_in[2];
    const float* W1   = (const float*)d_in[3];
    const float* b1   = (const float*)d_in[4];
    const float* W2   = (const float*)d_in[5];
    const float* b2   = (const float*)d_in[6];
    const float* W3   = (const float*)d_in[7];
    const float* b3   = (const float*)d_in[8];
    const float* Wres = (const float*)d_in[9];
    const float* g1   = (const float*)d_in[10];
    const float* be1  = (const float*)d_in[11];
    const float* m1   = (const float*)d_in[12];
    const float* v1   = (const float*)d_in[13];
    const float* g2   = (const float*)d_in[14];
    const float* be2  = (const float*)d_in[15];
    const float* m2   = (const float*)d_in[16];
    const float* v2   = (const float*)d_in[17];
    float* out = (float*)d_out;
    (void)n_in;

    const int N  = out_size;          // 100000
    const int E  = in_sizes[1] / 2;   // 1600000
    const int K1 = in_sizes[0] / N;   // 256

    const int T = 256;
    int nb_N    = (N + T - 1) / T;
    int nb_E    = (E + T - 1) / T;
    int nb_M    = (N + 127) / 128;
    int nb_warp = (N * 32 + T - 1) / T;

    static cudaStream_t s_csr = nullptr, s_g1 = nullptr, s_gr = nullptr;
    static cudaEvent_t  e_fork = nullptr, e_csr = nullptr, e_g1 = nullptr, e_gr = nullptr;
    if (!s_csr) {
        cudaStreamCreateWithFlags(&s_csr, cudaStreamNonBlocking);
        cudaStreamCreateWithFlags(&s_g1,  cudaStreamNonBlocking);
        cudaStreamCreateWithFlags(&s_gr,  cudaStreamNonBlocking);
        cudaEventCreateWithFlags(&e_fork, cudaEventDisableTiming);
        cudaEventCreateWithFlags(&e_csr,  cudaEventDisableTiming);
        cudaEventCreateWithFlags(&e_g1,   cudaEventDisableTiming);
        cudaEventCreateWithFlags(&e_gr,   cudaEventDisableTiming);
    }

    // fork
    cudaEventRecord(e_fork, 0);
    cudaStreamWaitEvent(s_csr, e_fork, 0);
    cudaStreamWaitEvent(s_g1,  e_fork, 0);
    cudaStreamWaitEvent(s_gr,  e_fork, 0);

    // --- bucket CSR build (stream s_csr): 3 kernels, 1 edge pass ---
    k_init<<<nb_N, T, 0, s_csr>>>(N);
    k_fill_bucket<<<nb_E, T, 0, s_csr>>>(ei, ew, E);
    k_dis<<<nb_N, T, 0, s_csr>>>(N);
    cudaEventRecord(e_csr, s_csr);

    // --- layer 1 GEMMs (parallel streams) ---
    gemm_bf16x3<<<nb_M, T, 0, s_g1>>>(x, -1, W1,   SEL_A, N, K1);
    cudaEventRecord(e_g1, s_g1);
    gemm_bf16x3<<<nb_M, T, 0, s_gr>>>(x, -1, Wres, SEL_R, N, K1);
    cudaEventRecord(e_gr, s_gr);

    // join CSR + GEMM1 before gather1
    cudaStreamWaitEvent(0, e_csr, 0);
    cudaStreamWaitEvent(0, e_g1, 0);

    // --- propagate 1 (gather, fused epilogue) ---
    k_gather_ep<<<nb_warp, T>>>(SEL_A, SEL_B, b1, g1, be1, m1, v1, -1, nullptr, N);

    // --- layer 2: h2_pre = h1@W2 ---
    gemm_bf16x3<<<nb_M, T>>>(nullptr, SEL_B, W2, SEL_A, N, 128);

    // join GEMMres before gather2 (its only consumer)
    cudaStreamWaitEvent(0, e_gr, 0);

    // --- propagate 2 (gather, fused epilogue + residual + GEMV w3) ---
    k_gather_ep<<<nb_warp, T>>>(SEL_A, SEL_B, b2, g2, be2, m2, v2, SEL_R, W3, N);

    // --- layer 3: scalar gather ---
    k_out<<<nb_warp, T>>>(b3, out, N);
}

// round 11
// speedup vs baseline: 1.1412x; 1.1412x over previous
#include <cuda_runtime.h>
#include <cuda_bf16.h>
#include <mma.h>
#include <math.h>

using namespace nvcuda;

#define NN 100000
#define EE 1600000
#define HH 128
#define NPAD (NN + 128)
#define SCAN_B 512
#define SCAN_NB ((NN + SCAN_B - 1) / SCAN_B)   // 196

// ---------------- scratch ----------------------------------------------------
__device__ float4 g_bufA4[(size_t)NPAD * HH / 4];
__device__ float4 g_bufB4[(size_t)NPAD * HH / 4];
__device__ float4 g_res4 [(size_t)NPAD * HH / 4];
__device__ float  g_dis [NN];
__device__ float  g_deg [NN];
__device__ float  g_s   [NN];
__device__ int    g_cnt [NN];
__device__ int    g_cur [NN];
__device__ int    g_partial[NN];
__device__ int    g_bsum[SCAN_B];
__device__ int    g_rowptr[NN + 1];
__device__ int    g_srcs[EE];
__device__ float  g_wS [EE];

#define SEL_A 0
#define SEL_B 1
#define SEL_R 2
__device__ __forceinline__ float* pick(int sel) {
    return sel == SEL_A ? (float*)g_bufA4
         : (sel == SEL_B ? (float*)g_bufB4 : (float*)g_res4);
}

// ---------------- exact CSR build --------------------------------------------
__global__ void k_init(int n) {
    int i = blockIdx.x * blockDim.x + threadIdx.x;
    if (i < n) { g_deg[i] = 1.0f; g_cnt[i] = 0; g_cur[i] = 0; }
}

__global__ void k_edge_count(const int* __restrict__ ei,
                             const float* __restrict__ ew, int E) {
    int e = blockIdx.x * blockDim.x + threadIdx.x;
    if (e < E) {
        int c = ei[E + e];
        atomicAdd(&g_deg[c], ew[e]);
        atomicAdd(&g_cnt[c], 1);
    }
}

__global__ void k_scan1(int n) {
    __shared__ int sh[SCAN_B];
    int i = blockIdx.x * SCAN_B + threadIdx.x;
    int v = (i < n) ? g_cnt[i] : 0;
    sh[threadIdx.x] = v;
    __syncthreads();
    for (int o = 1; o < SCAN_B; o <<= 1) {
        int t = (threadIdx.x >= o) ? sh[threadIdx.x - o] : 0;
        __syncthreads();
        sh[threadIdx.x] += t;
        __syncthreads();
    }
    if (i < n) g_partial[i] = sh[threadIdx.x] - v;
    if (threadIdx.x == SCAN_B - 1) g_bsum[blockIdx.x] = sh[threadIdx.x];
}

__global__ void k_scan2(int nb) {
    __shared__ int sh[SCAN_B];
    int v = (threadIdx.x < nb) ? g_bsum[threadIdx.x] : 0;
    sh[threadIdx.x] = v;
    __syncthreads();
    for (int o = 1; o < SCAN_B; o <<= 1) {
        int t = (threadIdx.x >= o) ? sh[threadIdx.x - o] : 0;
        __syncthreads();
        sh[threadIdx.x] += t;
        __syncthreads();
    }
    if (threadIdx.x < nb) g_bsum[threadIdx.x] = sh[threadIdx.x] - v;
}

__global__ void k_scan3(int n, int E) {
    int i = blockIdx.x * blockDim.x + threadIdx.x;
    if (i < n) {
        g_rowptr[i] = g_partial[i] + g_bsum[i / SCAN_B];
        g_dis[i] = rsqrtf(g_deg[i]);
    }
    if (i == 0) g_rowptr[n] = E;
}

__global__ void k_fillcsr(const int* __restrict__ ei,
                          const float* __restrict__ ew, int E) {
    int e = blockIdx.x * blockDim.x + threadIdx.x;
    if (e < E) {
        int r = ei[e];
        int c = ei[E + e];
        int pos = g_rowptr[c] + atomicAdd(&g_cur[c], 1);
        g_srcs[pos] = r;
        g_wS[pos]   = g_dis[r] * ew[e] * g_dis[c];
    }
}

// ---------------- bf16x3 tensor-core GEMM (occupancy-tuned) ------------------
// Block 128x128, BK=32, 8 warps (2x4), warp tile 64x32.
// No register prefetch; A-fragments scoped inside the i-loop; 2 CTAs/SM.
#define ASTR 40
#define BSTR 136
__global__ __launch_bounds__(256, 2)
void gemm_bf16x3(const float* __restrict__ A_ext, int selA,
                 const float* __restrict__ B, int selC, int M, int K) {
    const float* A = (selA < 0) ? A_ext : pick(selA);
    float* C = pick(selC);

    __shared__ __nv_bfloat16 AsH[128][ASTR], AsL[128][ASTR];
    __shared__ __nv_bfloat16 BsH[32][BSTR],  BsL[32][BSTR];

    int tid = threadIdx.x;
    int wid = tid >> 5;
    int warpM = wid >> 2;     // 0..1 -> 64 rows
    int warpN = wid & 3;      // 0..3 -> 32 cols
    int row0 = blockIdx.x * 128;

    wmma::fragment<wmma::accumulator, 16, 16, 16, float> acc[4][2];
    #pragma unroll
    for (int i = 0; i < 4; i++)
        #pragma unroll
        for (int j = 0; j < 2; j++) wmma::fill_fragment(acc[i][j], 0.0f);

    int ar = tid >> 3;            // 0..31
    int ac = (tid & 7) * 4;       // 0..28
    int br = tid >> 6;            // 0..3
    int bc = (tid & 63) * 2;      // 0..126

    for (int k0 = 0; k0 < K; k0 += 32) {
        // A tile: 128x32 fp32 -> bf16 hi/lo
        #pragma unroll
        for (int p = 0; p < 4; p++) {
            int r = ar + p * 32;
            int gr = row0 + r;
            float4 v = make_float4(0.f, 0.f, 0.f, 0.f);
            if (gr < M) v = *(const float4*)(A + (size_t)gr * K + k0 + ac);
            __nv_bfloat16 hx = __float2bfloat16(v.x);
            __nv_bfloat16 hy = __float2bfloat16(v.y);
            __nv_bfloat16 hz = __float2bfloat16(v.z);
            __nv_bfloat16 hw = __float2bfloat16(v.w);
            AsH[r][ac+0] = hx; AsL[r][ac+0] = __float2bfloat16(v.x - __bfloat162float(hx));
            AsH[r][ac+1] = hy; AsL[r][ac+1] = __float2bfloat16(v.y - __bfloat162float(hy));
            AsH[r][ac+2] = hz; AsL[r][ac+2] = __float2bfloat16(v.z - __bfloat162float(hz));
            AsH[r][ac+3] = hw; AsL[r][ac+3] = __float2bfloat16(v.w - __bfloat162float(hw));
        }
        // B tile: 32x128 fp32 -> bf16 hi/lo
        #pragma unroll
        for (int p = 0; p < 8; p++) {
            int r = br + p * 4;
            float2 v = *(const float2*)(B + (size_t)(k0 + r) * 128 + bc);
            __nv_bfloat16 hx = __float2bfloat16(v.x);
            __nv_bfloat16 hy = __float2bfloat16(v.y);
            BsH[r][bc+0] = hx; BsL[r][bc+0] = __float2bfloat16(v.x - __bfloat162float(hx));
            BsH[r][bc+1] = hy; BsL[r][bc+1] = __float2bfloat16(v.y - __bfloat162float(hy));
        }
        __syncthreads();

        #pragma unroll
        for (int kk = 0; kk < 32; kk += 16) {
            wmma::fragment<wmma::matrix_b, 16, 16, 16, __nv_bfloat16, wmma::row_major> bh[2], bl[2];
            #pragma unroll
            for (int j = 0; j < 2; j++) {
                wmma::load_matrix_sync(bh[j], &BsH[kk][warpN * 32 + j * 16], BSTR);
                wmma::load_matrix_sync(bl[j], &BsL[kk][warpN * 32 + j * 16], BSTR);
            }
            #pragma unroll
            for (int i = 0; i < 4; i++) {
                wmma::fragment<wmma::matrix_a, 16, 16, 16, __nv_bfloat16, wmma::row_major> ah, al;
                wmma::load_matrix_sync(ah, &AsH[warpM * 64 + i * 16][kk], ASTR);
                wmma::load_matrix_sync(al, &AsL[warpM * 64 + i * 16][kk], ASTR);
                #pragma unroll
                for (int j = 0; j < 2; j++) {
                    wmma::mma_sync(acc[i][j], al, bh[j], acc[i][j]);
                    wmma::mma_sync(acc[i][j], ah, bl[j], acc[i][j]);
                    wmma::mma_sync(acc[i][j], ah, bh[j], acc[i][j]);
                }
            }
        }
        __syncthreads();
    }

    #pragma unroll
    for (int i = 0; i < 4; i++)
        #pragma unroll
        for (int j = 0; j < 2; j++) {
            float* cp = C + (size_t)(row0 + warpM * 64 + i * 16) * 128 + warpN * 32 + j * 16;
            wmma::store_matrix_sync(cp, acc[i][j], 128, wmma::mem_row_major);
        }
}

// ---------------- fused CSR gather + selfloop + bias (+res) + BN + ReLU ------
__global__ __launch_bounds__(256)
void k_gather_ep(int selH, int selOut,
                 const float* __restrict__ bvec,
                 const float* __restrict__ g, const float* __restrict__ be,
                 const float* __restrict__ m, const float* __restrict__ v,
                 int selRes, const float* __restrict__ w3, int n) {
    int warp = (blockIdx.x * blockDim.x + threadIdx.x) >> 5;
    if (warp >= n) return;
    int lane = threadIdx.x & 31;
    const float* h = pick(selH);

    float d = g_dis[warp];
    float d2 = d * d;
    float4 p = *(const float4*)(h + (size_t)warp * 128 + lane * 4);
    float4 a;
    a.x = p.x * d2; a.y = p.y * d2; a.z = p.z * d2; a.w = p.w * d2;

    int beg = __ldg(&g_rowptr[warp]), end = __ldg(&g_rowptr[warp + 1]);
    int k = beg;
    for (; k + 3 < end; k += 4) {
        int   ri[4]; float wi[4];
        #pragma unroll
        for (int u = 0; u < 4; u++) { ri[u] = __ldg(&g_srcs[k + u]); wi[u] = __ldg(&g_wS[k + u]); }
        float4 hv[4];
        #pragma unroll
        for (int u = 0; u < 4; u++)
            hv[u] = *(const float4*)(h + (size_t)ri[u] * 128 + lane * 4);
        #pragma unroll
        for (int u = 0; u < 4; u++) {
            a.x += hv[u].x * wi[u];
            a.y += hv[u].y * wi[u];
            a.z += hv[u].z * wi[u];
            a.w += hv[u].w * wi[u];
        }
    }
    for (; k < end; k++) {
        int   r0 = __ldg(&g_srcs[k]);
        float w0 = __ldg(&g_wS[k]);
        float4 h0 = *(const float4*)(h + (size_t)r0 * 128 + lane * 4);
        a.x += h0.x * w0; a.y += h0.y * w0; a.z += h0.z * w0; a.w += h0.w * w0;
    }

    int j4 = lane * 4;
    float4 bv = *(const float4*)(bvec + j4);
    a.x += bv.x; a.y += bv.y; a.z += bv.z; a.w += bv.w;
    if (selRes >= 0) {
        float4 rr = *(const float4*)(pick(selRes) + (size_t)warp * 128 + j4);
        a.x += rr.x; a.y += rr.y; a.z += rr.z; a.w += rr.w;
    }
    float4 gv = *(const float4*)(g + j4);
    float4 vv = *(const float4*)(v + j4);
    float4 mv = *(const float4*)(m + j4);
    float4 bb = *(const float4*)(be + j4);
    float4 o;
    o.x = fmaxf((a.x - mv.x) * (gv.x * rsqrtf(vv.x + 1e-5f)) + bb.x, 0.f);
    o.y = fmaxf((a.y - mv.y) * (gv.y * rsqrtf(vv.y + 1e-5f)) + bb.y, 0.f);
    o.z = fmaxf((a.z - mv.z) * (gv.z * rsqrtf(vv.z + 1e-5f)) + bb.z, 0.f);
    o.w = fmaxf((a.w - mv.w) * (gv.w * rsqrtf(vv.w + 1e-5f)) + bb.w, 0.f);
    *(float4*)(pick(selOut) + (size_t)warp * 128 + j4) = o;

    if (w3) {   // fused GEMV: s = o . w3
        float4 wv = ((const float4*)w3)[lane];
        float s = o.x * wv.x + o.y * wv.y + o.z * wv.z + o.w * wv.w;
        #pragma unroll
        for (int off = 16; off > 0; off >>= 1) s += __shfl_down_sync(0xffffffffu, s, off);
        if (lane == 0) g_s[warp] = s;
    }
}

// ---------------- layer 3: warp-per-node scalar CSR gather -------------------
__global__ __launch_bounds__(256)
void k_out(const float* __restrict__ b3, float* __restrict__ out, int n) {
    int warp = (blockIdx.x * blockDim.x + threadIdx.x) >> 5;
    if (warp >= n) return;
    int lane = threadIdx.x & 31;
    int beg = __ldg(&g_rowptr[warp]), end = __ldg(&g_rowptr[warp + 1]);
    float acc = 0.0f;
    for (int k = beg + lane; k < end; k += 32)
        acc += g_s[__ldg(&g_srcs[k])] * __ldg(&g_wS[k]);
    #pragma unroll
    for (int off = 16; off > 0; off >>= 1) acc += __shfl_down_sync(0xffffffffu, acc, off);
    if (lane == 0) {
        float d = g_dis[warp];
        out[warp] = b3[0] + g_s[warp] * d * d + acc;
    }
}

// ---------------- launch ----------------------------------------------------
extern "C" void kernel_launch(void* const* d_in, const int* in_sizes, int n_in,
                              void* d_out, int out_size) {
    const float* x    = (const float*)d_in[0];
    const int*   ei   = (const int*)d_in[1];     // int32 (JAX x64 disabled)
    const float* ew   = (const float*)d_in[2];
    const float* W1   = (const float*)d_in[3];
    const float* b1   = (const float*)d_in[4];
    const float* W2   = (const float*)d_in[5];
    const float* b2   = (const float*)d_in[6];
    const float* W3   = (const float*)d_in[7];
    const float* b3   = (const float*)d_in[8];
    const float* Wres = (const float*)d_in[9];
    const float* g1   = (const float*)d_in[10];
    const float* be1  = (const float*)d_in[11];
    const float* m1   = (const float*)d_in[12];
    const float* v1   = (const float*)d_in[13];
    const float* g2   = (const float*)d_in[14];
    const float* be2  = (const float*)d_in[15];
    const float* m2   = (const float*)d_in[16];
    const float* v2   = (const float*)d_in[17];
    float* out = (float*)d_out;
    (void)n_in;

    const int N  = out_size;          // 100000
    const int E  = in_sizes[1] / 2;   // 1600000
    const int K1 = in_sizes[0] / N;   // 256

    const int T = 256;
    int nb_N    = (N + T - 1) / T;
    int nb_E    = (E + T - 1) / T;
    int nb_M    = (N + 127) / 128;
    int nb_warp = (N * 32 + T - 1) / T;

    static cudaStream_t s_csr = nullptr, s_g1 = nullptr, s_gr = nullptr;
    static cudaEvent_t  e_fork = nullptr, e_csr = nullptr, e_g1 = nullptr, e_gr = nullptr;
    if (!s_csr) {
        cudaStreamCreateWithFlags(&s_csr, cudaStreamNonBlocking);
        cudaStreamCreateWithFlags(&s_g1,  cudaStreamNonBlocking);
        cudaStreamCreateWithFlags(&s_gr,  cudaStreamNonBlocking);
        cudaEventCreateWithFlags(&e_fork, cudaEventDisableTiming);
        cudaEventCreateWithFlags(&e_csr,  cudaEventDisableTiming);
        cudaEventCreateWithFlags(&e_g1,   cudaEventDisableTiming);
        cudaEventCreateWithFlags(&e_gr,   cudaEventDisableTiming);
    }

    // fork
    cudaEventRecord(e_fork, 0);
    cudaStreamWaitEvent(s_csr, e_fork, 0);
    cudaStreamWaitEvent(s_g1,  e_fork, 0);
    cudaStreamWaitEvent(s_gr,  e_fork, 0);

    // --- CSR build + normalization (stream s_csr) ---
    k_init<<<nb_N, T, 0, s_csr>>>(N);
    k_edge_count<<<nb_E, T, 0, s_csr>>>(ei, ew, E);
    k_scan1<<<SCAN_NB, SCAN_B, 0, s_csr>>>(N);
    k_scan2<<<1, SCAN_B, 0, s_csr>>>(SCAN_NB);
    k_scan3<<<nb_N, T, 0, s_csr>>>(N, E);
    k_fillcsr<<<nb_E, T, 0, s_csr>>>(ei, ew, E);
    cudaEventRecord(e_csr, s_csr);

    // --- layer 1 GEMMs (parallel streams) ---
    gemm_bf16x3<<<nb_M, T, 0, s_g1>>>(x, -1, W1,   SEL_A, N, K1);
    cudaEventRecord(e_g1, s_g1);
    gemm_bf16x3<<<nb_M, T, 0, s_gr>>>(x, -1, Wres, SEL_R, N, K1);
    cudaEventRecord(e_gr, s_gr);

    // join CSR + GEMM1 before gather1
    cudaStreamWaitEvent(0, e_csr, 0);
    cudaStreamWaitEvent(0, e_g1, 0);

    // --- propagate 1 (gather, fused epilogue) ---
    k_gather_ep<<<nb_warp, T>>>(SEL_A, SEL_B, b1, g1, be1, m1, v1, -1, nullptr, N);

    // --- layer 2: h2_pre = h1@W2 ---
    gemm_bf16x3<<<nb_M, T>>>(nullptr, SEL_B, W2, SEL_A, N, 128);

    // join GEMMres before gather2 (its only consumer)
    cudaStreamWaitEvent(0, e_gr, 0);

    // --- propagate 2 (gather, fused epilogue + residual + GEMV w3) ---
    k_gather_ep<<<nb_warp, T>>>(SEL_A, SEL_B, b2, g2, be2, m2, v2, SEL_R, W3, N);

    // --- layer 3: scalar gather ---
    k_out<<<nb_warp, T>>>(b3, out, N);
}

// round 13
// speedup vs baseline: 1.2234x; 1.0721x over previous
#include <cuda_runtime.h>
#include <cuda_bf16.h>
#include <mma.h>
#include <math.h>

using namespace nvcuda;

#define NN 100000
#define EE 1600000
#define HH 128
#define NPAD (NN + 128)
#define SCAN_B 512
#define SCAN_NB ((NN + SCAN_B - 1) / SCAN_B)   // 196
#define NHALF 50048                            // pipeline split (multiple of 128)

// ---------------- scratch ----------------------------------------------------
__device__ float4 g_bufA4[(size_t)NPAD * HH / 4];
__device__ float4 g_bufB4[(size_t)NPAD * HH / 4];
__device__ float4 g_res4 [(size_t)NPAD * HH / 4];
__device__ float4 g_bufC4[(size_t)NPAD * HH / 4];
__device__ float  g_dis [NN];
__device__ float  g_deg [NN];
__device__ float  g_s   [NN];
__device__ int    g_cnt [NN];
__device__ int    g_cur [NN];
__device__ int    g_partial[NN];
__device__ int    g_bsum[SCAN_B];
__device__ int    g_rowptr[NN + 1];
__device__ int    g_srcs[EE];
__device__ float  g_wS [EE];

#define SEL_A 0
#define SEL_B 1
#define SEL_R 2
#define SEL_C 3
__device__ __forceinline__ float* pick(int sel) {
    if (sel == SEL_A) return (float*)g_bufA4;
    if (sel == SEL_B) return (float*)g_bufB4;
    if (sel == SEL_R) return (float*)g_res4;
    return (float*)g_bufC4;
}

// ---------------- exact CSR build --------------------------------------------
__global__ void k_init(int n) {
    int i = blockIdx.x * blockDim.x + threadIdx.x;
    if (i < n) { g_deg[i] = 1.0f; g_cnt[i] = 0; g_cur[i] = 0; }
}

__global__ void k_edge_count(const int* __restrict__ ei,
                             const float* __restrict__ ew, int E) {
    int e = blockIdx.x * blockDim.x + threadIdx.x;
    if (e < E) {
        int c = ei[E + e];
        atomicAdd(&g_deg[c], ew[e]);
        atomicAdd(&g_cnt[c], 1);
    }
}

__global__ void k_scan1(int n) {
    __shared__ int sh[SCAN_B];
    int i = blockIdx.x * SCAN_B + threadIdx.x;
    int v = (i < n) ? g_cnt[i] : 0;
    sh[threadIdx.x] = v;
    __syncthreads();
    for (int o = 1; o < SCAN_B; o <<= 1) {
        int t = (threadIdx.x >= o) ? sh[threadIdx.x - o] : 0;
        __syncthreads();
        sh[threadIdx.x] += t;
        __syncthreads();
    }
    if (i < n) g_partial[i] = sh[threadIdx.x] - v;
    if (threadIdx.x == SCAN_B - 1) g_bsum[blockIdx.x] = sh[threadIdx.x];
}

__global__ void k_scan2(int nb) {
    __shared__ int sh[SCAN_B];
    int v = (threadIdx.x < nb) ? g_bsum[threadIdx.x] : 0;
    sh[threadIdx.x] = v;
    __syncthreads();
    for (int o = 1; o < SCAN_B; o <<= 1) {
        int t = (threadIdx.x >= o) ? sh[threadIdx.x - o] : 0;
        __syncthreads();
        sh[threadIdx.x] += t;
        __syncthreads();
    }
    if (threadIdx.x < nb) g_bsum[threadIdx.x] = sh[threadIdx.x] - v;
}

__global__ void k_scan3(int n, int E) {
    int i = blockIdx.x * blockDim.x + threadIdx.x;
    if (i < n) {
        g_rowptr[i] = g_partial[i] + g_bsum[i / SCAN_B];
        g_dis[i] = rsqrtf(g_deg[i]);
    }
    if (i == 0) g_rowptr[n] = E;
}

__global__ void k_fillcsr(const int* __restrict__ ei,
                          const float* __restrict__ ew, int E) {
    int e = blockIdx.x * blockDim.x + threadIdx.x;
    if (e < E) {
        int r = ei[e];
        int c = ei[E + e];
        int pos = g_rowptr[c] + atomicAdd(&g_cur[c], 1);
        g_srcs[pos] = r;
        g_wS[pos]   = g_dis[r] * ew[e] * g_dis[c];
    }
}

// ---------------- bf16x3 tensor-core GEMM (occupancy-tuned) ------------------
#define ASTR 40
#define BSTR 136
__global__ __launch_bounds__(256, 2)
void gemm_bf16x3(const float* __restrict__ A_ext, int selA,
                 const float* __restrict__ B, int selC, int M, int K,
                 int row_base) {
    const float* A = (selA < 0) ? A_ext : pick(selA);
    float* C = pick(selC);

    __shared__ __nv_bfloat16 AsH[128][ASTR], AsL[128][ASTR];
    __shared__ __nv_bfloat16 BsH[32][BSTR],  BsL[32][BSTR];

    int tid = threadIdx.x;
    int wid = tid >> 5;
    int warpM = wid >> 2;
    int warpN = wid & 3;
    int row0 = row_base + blockIdx.x * 128;

    wmma::fragment<wmma::accumulator, 16, 16, 16, float> acc[4][2];
    #pragma unroll
    for (int i = 0; i < 4; i++)
        #pragma unroll
        for (int j = 0; j < 2; j++) wmma::fill_fragment(acc[i][j], 0.0f);

    int ar = tid >> 3;
    int ac = (tid & 7) * 4;
    int br = tid >> 6;
    int bc = (tid & 63) * 2;

    for (int k0 = 0; k0 < K; k0 += 32) {
        #pragma unroll
        for (int p = 0; p < 4; p++) {
            int r = ar + p * 32;
            int gr = row0 + r;
            float4 v = make_float4(0.f, 0.f, 0.f, 0.f);
            if (gr < M) v = *(const float4*)(A + (size_t)gr * K + k0 + ac);
            __nv_bfloat16 hx = __float2bfloat16(v.x);
            __nv_bfloat16 hy = __float2bfloat16(v.y);
            __nv_bfloat16 hz = __float2bfloat16(v.z);
            __nv_bfloat16 hw = __float2bfloat16(v.w);
            AsH[r][ac+0] = hx; AsL[r][ac+0] = __float2bfloat16(v.x - __bfloat162float(hx));
            AsH[r][ac+1] = hy; AsL[r][ac+1] = __float2bfloat16(v.y - __bfloat162float(hy));
            AsH[r][ac+2] = hz; AsL[r][ac+2] = __float2bfloat16(v.z - __bfloat162float(hz));
            AsH[r][ac+3] = hw; AsL[r][ac+3] = __float2bfloat16(v.w - __bfloat162float(hw));
        }
        #pragma unroll
        for (int p = 0; p < 8; p++) {
            int r = br + p * 4;
            float2 v = *(const float2*)(B + (size_t)(k0 + r) * 128 + bc);
            __nv_bfloat16 hx = __float2bfloat16(v.x);
            __nv_bfloat16 hy = __float2bfloat16(v.y);
            BsH[r][bc+0] = hx; BsL[r][bc+0] = __float2bfloat16(v.x - __bfloat162float(hx));
            BsH[r][bc+1] = hy; BsL[r][bc+1] = __float2bfloat16(v.y - __bfloat162float(hy));
        }
        __syncthreads();

        #pragma unroll
        for (int kk = 0; kk < 32; kk += 16) {
            wmma::fragment<wmma::matrix_b, 16, 16, 16, __nv_bfloat16, wmma::row_major> bh[2], bl[2];
            #pragma unroll
            for (int j = 0; j < 2; j++) {
                wmma::load_matrix_sync(bh[j], &BsH[kk][warpN * 32 + j * 16], BSTR);
                wmma::load_matrix_sync(bl[j], &BsL[kk][warpN * 32 + j * 16], BSTR);
            }
            #pragma unroll
            for (int i = 0; i < 4; i++) {
                wmma::fragment<wmma::matrix_a, 16, 16, 16, __nv_bfloat16, wmma::row_major> ah, al;
                wmma::load_matrix_sync(ah, &AsH[warpM * 64 + i * 16][kk], ASTR);
                wmma::load_matrix_sync(al, &AsL[warpM * 64 + i * 16][kk], ASTR);
                #pragma unroll
                for (int j = 0; j < 2; j++) {
                    wmma::mma_sync(acc[i][j], al, bh[j], acc[i][j]);
                    wmma::mma_sync(acc[i][j], ah, bl[j], acc[i][j]);
                    wmma::mma_sync(acc[i][j], ah, bh[j], acc[i][j]);
                }
            }
        }
        __syncthreads();
    }

    #pragma unroll
    for (int i = 0; i < 4; i++)
        #pragma unroll
        for (int j = 0; j < 2; j++) {
            float* cp = C + (size_t)(row0 + warpM * 64 + i * 16) * 128 + warpN * 32 + j * 16;
            wmma::store_matrix_sync(cp, acc[i][j], 128, wmma::mem_row_major);
        }
}

// ---------------- fused CSR gather + selfloop + bias (+res) + BN + ReLU ------
// Node range [node_base, node_end). selOut < 0 => skip the row store (dead).
__global__ __launch_bounds__(256)
void k_gather_ep(int selH, int selOut,
                 const float* __restrict__ bvec,
                 const float* __restrict__ g, const float* __restrict__ be,
                 const float* __restrict__ m, const float* __restrict__ v,
                 int selRes, const float* __restrict__ w3,
                 int node_base, int node_end) {
    int warp = node_base + ((blockIdx.x * blockDim.x + threadIdx.x) >> 5);
    if (warp >= node_end) return;
    int lane = threadIdx.x & 31;
    const float* h = pick(selH);

    float d = g_dis[warp];
    float d2 = d * d;
    float4 p = *(const float4*)(h + (size_t)warp * 128 + lane * 4);
    float4 a;
    a.x = p.x * d2; a.y = p.y * d2; a.z = p.z * d2; a.w = p.w * d2;

    int beg = __ldg(&g_rowptr[warp]), end = __ldg(&g_rowptr[warp + 1]);
    int k = beg;
    for (; k + 3 < end; k += 4) {
        int   ri[4]; float wi[4];
        #pragma unroll
        for (int u = 0; u < 4; u++) { ri[u] = __ldg(&g_srcs[k + u]); wi[u] = __ldg(&g_wS[k + u]); }
        float4 hv[4];
        #pragma unroll
        for (int u = 0; u < 4; u++)
            hv[u] = *(const float4*)(h + (size_t)ri[u] * 128 + lane * 4);
        #pragma unroll
        for (int u = 0; u < 4; u++) {
            a.x += hv[u].x * wi[u];
            a.y += hv[u].y * wi[u];
            a.z += hv[u].z * wi[u];
            a.w += hv[u].w * wi[u];
        }
    }
    for (; k < end; k++) {
        int   r0 = __ldg(&g_srcs[k]);
        float w0 = __ldg(&g_wS[k]);
        float4 h0 = *(const float4*)(h + (size_t)r0 * 128 + lane * 4);
        a.x += h0.x * w0; a.y += h0.y * w0; a.z += h0.z * w0; a.w += h0.w * w0;
    }

    int j4 = lane * 4;
    float4 bv = *(const float4*)(bvec + j4);
    a.x += bv.x; a.y += bv.y; a.z += bv.z; a.w += bv.w;
    if (selRes >= 0) {
        float4 rr = *(const float4*)(pick(selRes) + (size_t)warp * 128 + j4);
        a.x += rr.x; a.y += rr.y; a.z += rr.z; a.w += rr.w;
    }
    float4 gv = *(const float4*)(g + j4);
    float4 vv = *(const float4*)(v + j4);
    float4 mv = *(const float4*)(m + j4);
    float4 bb = *(const float4*)(be + j4);
    float4 o;
    o.x = fmaxf((a.x - mv.x) * (gv.x * rsqrtf(vv.x + 1e-5f)) + bb.x, 0.f);
    o.y = fmaxf((a.y - mv.y) * (gv.y * rsqrtf(vv.y + 1e-5f)) + bb.y, 0.f);
    o.z = fmaxf((a.z - mv.z) * (gv.z * rsqrtf(vv.z + 1e-5f)) + bb.z, 0.f);
    o.w = fmaxf((a.w - mv.w) * (gv.w * rsqrtf(vv.w + 1e-5f)) + bb.w, 0.f);
    if (selOut >= 0)
        *(float4*)(pick(selOut) + (size_t)warp * 128 + j4) = o;

    if (w3) {   // fused GEMV: s = o . w3
        float4 wv = ((const float4*)w3)[lane];
        float s = o.x * wv.x + o.y * wv.y + o.z * wv.z + o.w * wv.w;
        #pragma unroll
        for (int off = 16; off > 0; off >>= 1) s += __shfl_down_sync(0xffffffffu, s, off);
        if (lane == 0) g_s[warp] = s;
    }
}

// ---------------- layer 3: warp-per-node scalar CSR gather -------------------
__global__ __launch_bounds__(256)
void k_out(const float* __restrict__ b3, float* __restrict__ out, int n) {
    int warp = (blockIdx.x * blockDim.x + threadIdx.x) >> 5;
    if (warp >= n) return;
    int lane = threadIdx.x & 31;
    int beg = __ldg(&g_rowptr[warp]), end = __ldg(&g_rowptr[warp + 1]);
    float acc = 0.0f;
    for (int k = beg + lane; k < end; k += 32)
        acc += g_s[__ldg(&g_srcs[k])] * __ldg(&g_wS[k]);
    #pragma unroll
    for (int off = 16; off > 0; off >>= 1) acc += __shfl_down_sync(0xffffffffu, acc, off);
    if (lane == 0) {
        float d = g_dis[warp];
        out[warp] = b3[0] + g_s[warp] * d * d + acc;
    }
}

// ---------------- launch ----------------------------------------------------
extern "C" void kernel_launch(void* const* d_in, const int* in_sizes, int n_in,
                              void* d_out, int out_size) {
    const float* x    = (const float*)d_in[0];
    const int*   ei   = (const int*)d_in[1];     // int32 (JAX x64 disabled)
    const float* ew   = (const float*)d_in[2];
    const float* W1   = (const float*)d_in[3];
    const float* b1   = (const float*)d_in[4];
    const float* W2   = (const float*)d_in[5];
    const float* b2   = (const float*)d_in[6];
    const float* W3   = (const float*)d_in[7];
    const float* b3   = (const float*)d_in[8];
    const float* Wres = (const float*)d_in[9];
    const float* g1   = (const float*)d_in[10];
    const float* be1  = (const float*)d_in[11];
    const float* m1   = (const float*)d_in[12];
    const float* v1   = (const float*)d_in[13];
    const float* g2   = (const float*)d_in[14];
    const float* be2  = (const float*)d_in[15];
    const float* m2   = (const float*)d_in[16];
    const float* v2   = (const float*)d_in[17];
    float* out = (float*)d_out;
    (void)n_in;

    const int N  = out_size;          // 100000
    const int E  = in_sizes[1] / 2;   // 1600000
    const int K1 = in_sizes[0] / N;   // 256

    const int T = 256;
    int nb_N    = (N + T - 1) / T;
    int nb_E    = (E + T - 1) / T;
    int nb_M    = (N + 127) / 128;
    int nb_warp = (N * 32 + T - 1) / T;

    const int H0 = NHALF;             // pipeline halves
    const int H1 = N - H0;
    int nb_h0 = (H0 * 32 + T - 1) / T;
    int nb_h1 = (H1 * 32 + T - 1) / T;
    int nb_M0 = (H0 + 127) / 128;
    int nb_M1 = (H1 + 127) / 128;

    static cudaStream_t s_csr = nullptr, s_g1 = nullptr, s_gr = nullptr;
    static cudaEvent_t  e_fork = nullptr, e_csr = nullptr, e_g1 = nullptr, e_gr = nullptr;
    static cudaEvent_t  e_h0 = nullptr, e_h1 = nullptr;
    if (!s_csr) {
        cudaStreamCreateWithFlags(&s_csr, cudaStreamNonBlocking);
        cudaStreamCreateWithFlags(&s_g1,  cudaStreamNonBlocking);
        cudaStreamCreateWithFlags(&s_gr,  cudaStreamNonBlocking);
        cudaEventCreateWithFlags(&e_fork, cudaEventDisableTiming);
        cudaEventCreateWithFlags(&e_csr,  cudaEventDisableTiming);
        cudaEventCreateWithFlags(&e_g1,   cudaEventDisableTiming);
        cudaEventCreateWithFlags(&e_gr,   cudaEventDisableTiming);
        cudaEventCreateWithFlags(&e_h0,   cudaEventDisableTiming);
        cudaEventCreateWithFlags(&e_h1,   cudaEventDisableTiming);
    }

    // fork
    cudaEventRecord(e_fork, 0);
    cudaStreamWaitEvent(s_csr, e_fork, 0);
    cudaStreamWaitEvent(s_g1,  e_fork, 0);
    cudaStreamWaitEvent(s_gr,  e_fork, 0);

    // --- CSR build + normalization (stream s_csr) ---
    k_init<<<nb_N, T, 0, s_csr>>>(N);
    k_edge_count<<<nb_E, T, 0, s_csr>>>(ei, ew, E);
    k_scan1<<<SCAN_NB, SCAN_B, 0, s_csr>>>(N);
    k_scan2<<<1, SCAN_B, 0, s_csr>>>(SCAN_NB);
    k_scan3<<<nb_N, T, 0, s_csr>>>(N, E);
    k_fillcsr<<<nb_E, T, 0, s_csr>>>(ei, ew, E);
    cudaEventRecord(e_csr, s_csr);

    // --- layer 1 GEMMs (parallel streams) ---
    gemm_bf16x3<<<nb_M, T, 0, s_g1>>>(x, -1, W1,   SEL_A, N, K1, 0);
    cudaEventRecord(e_g1, s_g1);
    gemm_bf16x3<<<nb_M, T, 0, s_gr>>>(x, -1, Wres, SEL_R, N, K1, 0);
    cudaEventRecord(e_gr, s_gr);

    // join CSR + GEMM-W1 before gather1
    cudaStreamWaitEvent(0, e_csr, 0);
    cudaStreamWaitEvent(0, e_g1, 0);

    // --- pipelined propagate1 / GEMM2 over two node halves ---
    // gather1: SEL_A -> SEL_B ; GEMM2: SEL_B -> SEL_C (no buffer reuse => no race)
    k_gather_ep<<<nb_h0, T>>>(SEL_A, SEL_B, b1, g1, be1, m1, v1, -1, nullptr, 0, H0);
    cudaEventRecord(e_h0, 0);

    // half1 gather on s_g1, concurrent with GEMM2-half0 on default
    cudaStreamWaitEvent(s_g1, e_h0, 0);
    k_gather_ep<<<nb_h1, T, 0, s_g1>>>(SEL_A, SEL_B, b1, g1, be1, m1, v1, -1, nullptr, H0, N);
    cudaEventRecord(e_h1, s_g1);

    gemm_bf16x3<<<nb_M0, T>>>(nullptr, SEL_B, W2, SEL_C, N, 128, 0);

    cudaStreamWaitEvent(0, e_h1, 0);
    gemm_bf16x3<<<nb_M1, T>>>(nullptr, SEL_B, W2, SEL_C, N, 128, H0);

    // join GEMM-Wres before gather2 (its only consumer)
    cudaStreamWaitEvent(0, e_gr, 0);

    // --- propagate 2: h2 rows are dead after s = h2.w3 -> skip the store ---
    k_gather_ep<<<nb_warp, T>>>(SEL_C, -1, b2, g2, be2, m2, v2, SEL_R, W3, 0, N);

    // --- layer 3: scalar gather ---
    k_out<<<nb_warp, T>>>(b3, out, N);
}

// round 14
// speedup vs baseline: 1.2502x; 1.0219x over previous
#include <cuda_runtime.h>
#include <cuda_bf16.h>
#include <mma.h>
#include <math.h>

using namespace nvcuda;

#define NN 100000
#define EE 1600000
#define HH 128
#define NPAD (NN + 128)
#define SCAN_B 512
#define SCAN_NB ((NN + SCAN_B - 1) / SCAN_B)   // 196
#define NHALF 50048                            // pipeline split (multiple of 128)

// ---------------- scratch ----------------------------------------------------
__device__ float4 g_bufA4[(size_t)NPAD * HH / 4];
__device__ float4 g_bufB4[(size_t)NPAD * HH / 4];
__device__ float4 g_res4 [(size_t)NPAD * HH / 4];
__device__ float4 g_bufC4[(size_t)NPAD * HH / 4];
__device__ float  g_dis [NN];
__device__ float  g_deg [NN];
__device__ float  g_s   [NN];
__device__ int    g_cnt [NN];
__device__ int    g_cur [NN];
__device__ int    g_partial[NN];
__device__ int    g_bsum[SCAN_B];
__device__ int    g_rowptr[NN + 1];
__device__ int    g_srcs[EE];
__device__ float  g_wS [EE];

#define SEL_A 0
#define SEL_B 1
#define SEL_R 2
#define SEL_C 3
__device__ __forceinline__ float* pick(int sel) {
    if (sel == SEL_A) return (float*)g_bufA4;
    if (sel == SEL_B) return (float*)g_bufB4;
    if (sel == SEL_R) return (float*)g_res4;
    return (float*)g_bufC4;
}

// ---------------- exact CSR build --------------------------------------------
__global__ void k_init(int n) {
    int i = blockIdx.x * blockDim.x + threadIdx.x;
    if (i < n) { g_deg[i] = 1.0f; g_cnt[i] = 0; g_cur[i] = 0; }
}

__global__ void k_edge_count(const int* __restrict__ ei,
                             const float* __restrict__ ew, int E) {
    int e = blockIdx.x * blockDim.x + threadIdx.x;
    if (e < E) {
        int c = ei[E + e];
        atomicAdd(&g_deg[c], ew[e]);
        atomicAdd(&g_cnt[c], 1);
    }
}

__global__ void k_scan1(int n) {
    __shared__ int sh[SCAN_B];
    int i = blockIdx.x * SCAN_B + threadIdx.x;
    int v = (i < n) ? g_cnt[i] : 0;
    sh[threadIdx.x] = v;
    __syncthreads();
    for (int o = 1; o < SCAN_B; o <<= 1) {
        int t = (threadIdx.x >= o) ? sh[threadIdx.x - o] : 0;
        __syncthreads();
        sh[threadIdx.x] += t;
        __syncthreads();
    }
    if (i < n) g_partial[i] = sh[threadIdx.x] - v;
    if (threadIdx.x == SCAN_B - 1) g_bsum[blockIdx.x] = sh[threadIdx.x];
}

__global__ void k_scan2(int nb) {
    __shared__ int sh[SCAN_B];
    int v = (threadIdx.x < nb) ? g_bsum[threadIdx.x] : 0;
    sh[threadIdx.x] = v;
    __syncthreads();
    for (int o = 1; o < SCAN_B; o <<= 1) {
        int t = (threadIdx.x >= o) ? sh[threadIdx.x - o] : 0;
        __syncthreads();
        sh[threadIdx.x] += t;
        __syncthreads();
    }
    if (threadIdx.x < nb) g_bsum[threadIdx.x] = sh[threadIdx.x] - v;
}

__global__ void k_scan3(int n, int E) {
    int i = blockIdx.x * blockDim.x + threadIdx.x;
    if (i < n) {
        g_rowptr[i] = g_partial[i] + g_bsum[i / SCAN_B];
        g_dis[i] = rsqrtf(g_deg[i]);
    }
    if (i == 0) g_rowptr[n] = E;
}

__global__ void k_fillcsr(const int* __restrict__ ei,
                          const float* __restrict__ ew, int E) {
    int e = blockIdx.x * blockDim.x + threadIdx.x;
    if (e < E) {
        int r = ei[e];
        int c = ei[E + e];
        int pos = g_rowptr[c] + atomicAdd(&g_cur[c], 1);
        g_srcs[pos] = r;
        g_wS[pos]   = g_dis[r] * ew[e] * g_dis[c];
    }
}

// ---------------- bf16x3 tensor-core GEMM (occupancy-tuned) ------------------
#define ASTR 40
#define BSTR 136
__global__ __launch_bounds__(256, 2)
void gemm_bf16x3(const float* __restrict__ A_ext, int selA,
                 const float* __restrict__ B, int selC, int M, int K,
                 int row_base) {
    const float* A = (selA < 0) ? A_ext : pick(selA);
    float* C = pick(selC);

    __shared__ __nv_bfloat16 AsH[128][ASTR], AsL[128][ASTR];
    __shared__ __nv_bfloat16 BsH[32][BSTR],  BsL[32][BSTR];

    int tid = threadIdx.x;
    int wid = tid >> 5;
    int warpM = wid >> 2;
    int warpN = wid & 3;
    int row0 = row_base + blockIdx.x * 128;

    wmma::fragment<wmma::accumulator, 16, 16, 16, float> acc[4][2];
    #pragma unroll
    for (int i = 0; i < 4; i++)
        #pragma unroll
        for (int j = 0; j < 2; j++) wmma::fill_fragment(acc[i][j], 0.0f);

    int ar = tid >> 3;
    int ac = (tid & 7) * 4;
    int br = tid >> 6;
    int bc = (tid & 63) * 2;

    for (int k0 = 0; k0 < K; k0 += 32) {
        #pragma unroll
        for (int p = 0; p < 4; p++) {
            int r = ar + p * 32;
            int gr = row0 + r;
            float4 v = make_float4(0.f, 0.f, 0.f, 0.f);
            if (gr < M) v = *(const float4*)(A + (size_t)gr * K + k0 + ac);
            __nv_bfloat16 hx = __float2bfloat16(v.x);
            __nv_bfloat16 hy = __float2bfloat16(v.y);
            __nv_bfloat16 hz = __float2bfloat16(v.z);
            __nv_bfloat16 hw = __float2bfloat16(v.w);
            AsH[r][ac+0] = hx; AsL[r][ac+0] = __float2bfloat16(v.x - __bfloat162float(hx));
            AsH[r][ac+1] = hy; AsL[r][ac+1] = __float2bfloat16(v.y - __bfloat162float(hy));
            AsH[r][ac+2] = hz; AsL[r][ac+2] = __float2bfloat16(v.z - __bfloat162float(hz));
            AsH[r][ac+3] = hw; AsL[r][ac+3] = __float2bfloat16(v.w - __bfloat162float(hw));
        }
        #pragma unroll
        for (int p = 0; p < 8; p++) {
            int r = br + p * 4;
            float2 v = *(const float2*)(B + (size_t)(k0 + r) * 128 + bc);
            __nv_bfloat16 hx = __float2bfloat16(v.x);
            __nv_bfloat16 hy = __float2bfloat16(v.y);
            BsH[r][bc+0] = hx; BsL[r][bc+0] = __float2bfloat16(v.x - __bfloat162float(hx));
            BsH[r][bc+1] = hy; BsL[r][bc+1] = __float2bfloat16(v.y - __bfloat162float(hy));
        }
        __syncthreads();

        #pragma unroll
        for (int kk = 0; kk < 32; kk += 16) {
            wmma::fragment<wmma::matrix_b, 16, 16, 16, __nv_bfloat16, wmma::row_major> bh[2], bl[2];
            #pragma unroll
            for (int j = 0; j < 2; j++) {
                wmma::load_matrix_sync(bh[j], &BsH[kk][warpN * 32 + j * 16], BSTR);
                wmma::load_matrix_sync(bl[j], &BsL[kk][warpN * 32 + j * 16], BSTR);
            }
            #pragma unroll
            for (int i = 0; i < 4; i++) {
                wmma::fragment<wmma::matrix_a, 16, 16, 16, __nv_bfloat16, wmma::row_major> ah, al;
                wmma::load_matrix_sync(ah, &AsH[warpM * 64 + i * 16][kk], ASTR);
                wmma::load_matrix_sync(al, &AsL[warpM * 64 + i * 16][kk], ASTR);
                #pragma unroll
                for (int j = 0; j < 2; j++) {
                    wmma::mma_sync(acc[i][j], al, bh[j], acc[i][j]);
                    wmma::mma_sync(acc[i][j], ah, bl[j], acc[i][j]);
                    wmma::mma_sync(acc[i][j], ah, bh[j], acc[i][j]);
                }
            }
        }
        __syncthreads();
    }

    #pragma unroll
    for (int i = 0; i < 4; i++)
        #pragma unroll
        for (int j = 0; j < 2; j++) {
            float* cp = C + (size_t)(row0 + warpM * 64 + i * 16) * 128 + warpN * 32 + j * 16;
            wmma::store_matrix_sync(cp, acc[i][j], 128, wmma::mem_row_major);
        }
}

// ---------------- fused CSR gather + selfloop + bias (+res) + BN + ReLU ------
// Node range [node_base, node_end). selOut < 0 => skip the row store (dead).
__global__ __launch_bounds__(256)
void k_gather_ep(int selH, int selOut,
                 const float* __restrict__ bvec,
                 const float* __restrict__ g, const float* __restrict__ be,
                 const float* __restrict__ m, const float* __restrict__ v,
                 int selRes, const float* __restrict__ w3,
                 int node_base, int node_end) {
    int warp = node_base + ((blockIdx.x * blockDim.x + threadIdx.x) >> 5);
    if (warp >= node_end) return;
    int lane = threadIdx.x & 31;
    const float* h = pick(selH);

    float d = g_dis[warp];
    float d2 = d * d;
    float4 p = *(const float4*)(h + (size_t)warp * 128 + lane * 4);
    float4 a;
    a.x = p.x * d2; a.y = p.y * d2; a.z = p.z * d2; a.w = p.w * d2;

    int beg = __ldg(&g_rowptr[warp]), end = __ldg(&g_rowptr[warp + 1]);
    int k = beg;
    for (; k + 3 < end; k += 4) {
        int   ri[4]; float wi[4];
        #pragma unroll
        for (int u = 0; u < 4; u++) { ri[u] = __ldg(&g_srcs[k + u]); wi[u] = __ldg(&g_wS[k + u]); }
        float4 hv[4];
        #pragma unroll
        for (int u = 0; u < 4; u++)
            hv[u] = *(const float4*)(h + (size_t)ri[u] * 128 + lane * 4);
        #pragma unroll
        for (int u = 0; u < 4; u++) {
            a.x += hv[u].x * wi[u];
            a.y += hv[u].y * wi[u];
            a.z += hv[u].z * wi[u];
            a.w += hv[u].w * wi[u];
        }
    }
    for (; k < end; k++) {
        int   r0 = __ldg(&g_srcs[k]);
        float w0 = __ldg(&g_wS[k]);
        float4 h0 = *(const float4*)(h + (size_t)r0 * 128 + lane * 4);
        a.x += h0.x * w0; a.y += h0.y * w0; a.z += h0.z * w0; a.w += h0.w * w0;
    }

    int j4 = lane * 4;
    float4 bv = *(const float4*)(bvec + j4);
    a.x += bv.x; a.y += bv.y; a.z += bv.z; a.w += bv.w;
    if (selRes >= 0) {
        float4 rr = *(const float4*)(pick(selRes) + (size_t)warp * 128 + j4);
        a.x += rr.x; a.y += rr.y; a.z += rr.z; a.w += rr.w;
    }
    float4 gv = *(const float4*)(g + j4);
    float4 vv = *(const float4*)(v + j4);
    float4 mv = *(const float4*)(m + j4);
    float4 bb = *(const float4*)(be + j4);
    float4 o;
    o.x = fmaxf((a.x - mv.x) * (gv.x * rsqrtf(vv.x + 1e-5f)) + bb.x, 0.f);
    o.y = fmaxf((a.y - mv.y) * (gv.y * rsqrtf(vv.y + 1e-5f)) + bb.y, 0.f);
    o.z = fmaxf((a.z - mv.z) * (gv.z * rsqrtf(vv.z + 1e-5f)) + bb.z, 0.f);
    o.w = fmaxf((a.w - mv.w) * (gv.w * rsqrtf(vv.w + 1e-5f)) + bb.w, 0.f);
    if (selOut >= 0)
        *(float4*)(pick(selOut) + (size_t)warp * 128 + j4) = o;

    if (w3) {   // fused GEMV: s = o . w3
        float4 wv = ((const float4*)w3)[lane];
        float s = o.x * wv.x + o.y * wv.y + o.z * wv.z + o.w * wv.w;
        #pragma unroll
        for (int off = 16; off > 0; off >>= 1) s += __shfl_down_sync(0xffffffffu, s, off);
        if (lane == 0) g_s[warp] = s;
    }
}

// ---------------- layer 3: warp-per-node scalar CSR gather -------------------
__global__ __launch_bounds__(256)
void k_out(const float* __restrict__ b3, float* __restrict__ out, int n) {
    int warp = (blockIdx.x * blockDim.x + threadIdx.x) >> 5;
    if (warp >= n) return;
    int lane = threadIdx.x & 31;
    int beg = __ldg(&g_rowptr[warp]), end = __ldg(&g_rowptr[warp + 1]);
    float acc = 0.0f;
    for (int k = beg + lane; k < end; k += 32)
        acc += g_s[__ldg(&g_srcs[k])] * __ldg(&g_wS[k]);
    #pragma unroll
    for (int off = 16; off > 0; off >>= 1) acc += __shfl_down_sync(0xffffffffu, acc, off);
    if (lane == 0) {
        float d = g_dis[warp];
        out[warp] = b3[0] + g_s[warp] * d * d + acc;
    }
}

// ---------------- launch ----------------------------------------------------
extern "C" void kernel_launch(void* const* d_in, const int* in_sizes, int n_in,
                              void* d_out, int out_size) {
    const float* x    = (const float*)d_in[0];
    const int*   ei   = (const int*)d_in[1];     // int32 (JAX x64 disabled)
    const float* ew   = (const float*)d_in[2];
    const float* W1   = (const float*)d_in[3];
    const float* b1   = (const float*)d_in[4];
    const float* W2   = (const float*)d_in[5];
    const float* b2   = (const float*)d_in[6];
    const float* W3   = (const float*)d_in[7];
    const float* b3   = (const float*)d_in[8];
    const float* Wres = (const float*)d_in[9];
    const float* g1   = (const float*)d_in[10];
    const float* be1  = (const float*)d_in[11];
    const float* m1   = (const float*)d_in[12];
    const float* v1   = (const float*)d_in[13];
    const float* g2   = (const float*)d_in[14];
    const float* be2  = (const float*)d_in[15];
    const float* m2   = (const float*)d_in[16];
    const float* v2   = (const float*)d_in[17];
    float* out = (float*)d_out;
    (void)n_in;

    const int N  = out_size;          // 100000
    const int E  = in_sizes[1] / 2;   // 1600000
    const int K1 = in_sizes[0] / N;   // 256

    const int T = 256;
    int nb_N    = (N + T - 1) / T;
    int nb_E    = (E + T - 1) / T;
    int nb_M    = (N + 127) / 128;
    int nb_warp = (N * 32 + T - 1) / T;

    const int H0 = NHALF;             // pipeline halves
    const int H1 = N - H0;
    int nb_h0 = (H0 * 32 + T - 1) / T;
    int nb_h1 = (H1 * 32 + T - 1) / T;
    int nb_M0 = (H0 + 127) / 128;
    int nb_M1 = (H1 + 127) / 128;

    static cudaStream_t s_csr = nullptr, s_g1 = nullptr, s_gr = nullptr;
    static cudaEvent_t  e_fork = nullptr, e_csr = nullptr, e_g1 = nullptr, e_gr = nullptr;
    static cudaEvent_t  e_h0 = nullptr, e_h1 = nullptr;
    if (!s_csr) {
        cudaStreamCreateWithFlags(&s_csr, cudaStreamNonBlocking);
        cudaStreamCreateWithFlags(&s_g1,  cudaStreamNonBlocking);
        cudaStreamCreateWithFlags(&s_gr,  cudaStreamNonBlocking);
        cudaEventCreateWithFlags(&e_fork, cudaEventDisableTiming);
        cudaEventCreateWithFlags(&e_csr,  cudaEventDisableTiming);
        cudaEventCreateWithFlags(&e_g1,   cudaEventDisableTiming);
        cudaEventCreateWithFlags(&e_gr,   cudaEventDisableTiming);
        cudaEventCreateWithFlags(&e_h0,   cudaEventDisableTiming);
        cudaEventCreateWithFlags(&e_h1,   cudaEventDisableTiming);
    }

    // fork
    cudaEventRecord(e_fork, 0);
    cudaStreamWaitEvent(s_csr, e_fork, 0);
    cudaStreamWaitEvent(s_g1,  e_fork, 0);

    // --- CSR build + normalization (stream s_csr) ---
    k_init<<<nb_N, T, 0, s_csr>>>(N);
    k_edge_count<<<nb_E, T, 0, s_csr>>>(ei, ew, E);
    k_scan1<<<SCAN_NB, SCAN_B, 0, s_csr>>>(N);
    k_scan2<<<1, SCAN_B, 0, s_csr>>>(SCAN_NB);
    k_scan3<<<nb_N, T, 0, s_csr>>>(N, E);
    k_fillcsr<<<nb_E, T, 0, s_csr>>>(ei, ew, E);
    cudaEventRecord(e_csr, s_csr);

    // --- layer 1: W1-GEMM only at the head (Wres deferred past it) ---
    gemm_bf16x3<<<nb_M, T, 0, s_g1>>>(x, -1, W1,   SEL_A, N, K1, 0);
    cudaEventRecord(e_g1, s_g1);

    // Wres-GEMM starts after W1 finishes: overlaps gather1 + GEMM2 region,
    // must only complete before gather2 (~140us of slack).
    cudaStreamWaitEvent(s_gr, e_g1, 0);
    gemm_bf16x3<<<nb_M, T, 0, s_gr>>>(x, -1, Wres, SEL_R, N, K1, 0);
    cudaEventRecord(e_gr, s_gr);

    // join CSR + GEMM-W1 before gather1
    cudaStreamWaitEvent(0, e_csr, 0);
    cudaStreamWaitEvent(0, e_g1, 0);

    // --- pipelined propagate1 / GEMM2 over two node halves ---
    // gather1: SEL_A -> SEL_B ; GEMM2: SEL_B -> SEL_C (no buffer reuse => no race)
    k_gather_ep<<<nb_h0, T>>>(SEL_A, SEL_B, b1, g1, be1, m1, v1, -1, nullptr, 0, H0);
    cudaEventRecord(e_h0, 0);

    // half1 gather on s_g1, concurrent with GEMM2-half0 on default
    cudaStreamWaitEvent(s_g1, e_h0, 0);
    k_gather_ep<<<nb_h1, T, 0, s_g1>>>(SEL_A, SEL_B, b1, g1, be1, m1, v1, -1, nullptr, H0, N);
    cudaEventRecord(e_h1, s_g1);

    gemm_bf16x3<<<nb_M0, T>>>(nullptr, SEL_B, W2, SEL_C, N, 128, 0);

    cudaStreamWaitEvent(0, e_h1, 0);
    gemm_bf16x3<<<nb_M1, T>>>(nullptr, SEL_B, W2, SEL_C, N, 128, H0);

    // join GEMM-Wres before gather2 (its only consumer)
    cudaStreamWaitEvent(0, e_gr, 0);

    // --- propagate 2: h2 rows are dead after s = h2.w3 -> skip the store ---
    k_gather_ep<<<nb_warp, T>>>(SEL_C, -1, b2, g2, be2, m2, v2, SEL_R, W3, 0, N);

    // --- layer 3: scalar gather ---
    k_out<<<nb_warp, T>>>(b3, out, N);
}

// round 16
// speedup vs baseline: 1.2533x; 1.0025x over previous
#include <cuda_runtime.h>
#include <cuda_bf16.h>
#include <cuda_fp16.h>
#include <mma.h>
#include <math.h>

using namespace nvcuda;

#define NN 100000
#define EE 1600000
#define HH 128
#define NPAD (NN + 128)
#define SCAN_B 512
#define SCAN_NB ((NN + SCAN_B - 1) / SCAN_B)   // 196
#define NHALF 50048                            // pipeline split (multiple of 128)

// ---------------- scratch ----------------------------------------------------
__device__ float4 g_bufB4[(size_t)NPAD * HH / 4];   // h1 (gather1 out, GEMM2 in) fp32
__device__ float4 g_res4 [(size_t)NPAD * HH / 4];   // residual fp32
__device__ __half g_hA[(size_t)NPAD * HH];          // h1_pre fp16 (gather1 in)
__device__ __half g_hC[(size_t)NPAD * HH];          // h2_pre fp16 (gather2 in)
__device__ float  g_dis [NN];
__device__ float  g_deg [NN];
__device__ float  g_s   [NN];
__device__ int    g_cnt [NN];
__device__ int    g_cur [NN];
__device__ int    g_partial[NN];
__device__ int    g_bsum[SCAN_B];
__device__ int    g_rowptr[NN + 1];
__device__ int    g_srcs[EE];
__device__ float  g_wS [EE];

#define SEL_B 1
#define SEL_R 2
__device__ __forceinline__ float* pick(int sel) {
    return sel == SEL_B ? (float*)g_bufB4 : (float*)g_res4;
}
__device__ __forceinline__ __half* pickH(int sel) {
    return sel == 0 ? g_hA : g_hC;
}

// ---------------- exact CSR build --------------------------------------------
__global__ void k_init(int n) {
    int i = blockIdx.x * blockDim.x + threadIdx.x;
    if (i < n) { g_deg[i] = 1.0f; g_cnt[i] = 0; g_cur[i] = 0; }
}

__global__ void k_edge_count(const int* __restrict__ ei,
                             const float* __restrict__ ew, int E) {
    int e = blockIdx.x * blockDim.x + threadIdx.x;
    if (e < E) {
        int c = ei[E + e];
        atomicAdd(&g_deg[c], ew[e]);
        atomicAdd(&g_cnt[c], 1);
    }
}

__global__ void k_scan1(int n) {
    __shared__ int sh[SCAN_B];
    int i = blockIdx.x * SCAN_B + threadIdx.x;
    int v = (i < n) ? g_cnt[i] : 0;
    sh[threadIdx.x] = v;
    __syncthreads();
    for (int o = 1; o < SCAN_B; o <<= 1) {
        int t = (threadIdx.x >= o) ? sh[threadIdx.x - o] : 0;
        __syncthreads();
        sh[threadIdx.x] += t;
        __syncthreads();
    }
    if (i < n) g_partial[i] = sh[threadIdx.x] - v;
    if (threadIdx.x == SCAN_B - 1) g_bsum[blockIdx.x] = sh[threadIdx.x];
}

__global__ void k_scan2(int nb) {
    __shared__ int sh[SCAN_B];
    int v = (threadIdx.x < nb) ? g_bsum[threadIdx.x] : 0;
    sh[threadIdx.x] = v;
    __syncthreads();
    for (int o = 1; o < SCAN_B; o <<= 1) {
        int t = (threadIdx.x >= o) ? sh[threadIdx.x - o] : 0;
        __syncthreads();
        sh[threadIdx.x] += t;
        __syncthreads();
    }
    if (threadIdx.x < nb) g_bsum[threadIdx.x] = sh[threadIdx.x] - v;
}

__global__ void k_scan3(int n, int E) {
    int i = blockIdx.x * blockDim.x + threadIdx.x;
    if (i < n) {
        g_rowptr[i] = g_partial[i] + g_bsum[i / SCAN_B];
        g_dis[i] = rsqrtf(g_deg[i]);
    }
    if (i == 0) g_rowptr[n] = E;
}

__global__ void k_fillcsr(const int* __restrict__ ei,
                          const float* __restrict__ ew, int E) {
    int e = blockIdx.x * blockDim.x + threadIdx.x;
    if (e < E) {
        int r = ei[e];
        int c = ei[E + e];
        int pos = g_rowptr[c] + atomicAdd(&g_cur[c], 1);
        g_srcs[pos] = r;
        g_wS[pos]   = g_dis[r] * ew[e] * g_dis[c];
    }
}

// ---------------- bf16x3 tensor-core GEMM (occupancy-tuned) ------------------
// selHC >= 0 : write C as fp16 into pickH(selHC) (for gather-only consumers).
// selHC <  0 : write fp32 into pick(selC).
#define ASTR 40
#define BSTR 136
#define STG_LD 20   // fp32 stage stride: multiple of 4 (16B row alignment for wmma)
__global__ __launch_bounds__(256, 2)
void gemm_bf16x3(const float* __restrict__ A_ext, int selA,
                 const float* __restrict__ B, int selC, int selHC,
                 int M, int K, int row_base) {
    const float* A = (selA < 0) ? A_ext : pick(selA);

    __shared__ __nv_bfloat16 AsH[128][ASTR], AsL[128][ASTR];
    __shared__ __nv_bfloat16 BsH[32][BSTR],  BsL[32][BSTR];

    int tid = threadIdx.x;
    int wid = tid >> 5;
    int lane = tid & 31;
    int warpM = wid >> 2;
    int warpN = wid & 3;
    int row0 = row_base + blockIdx.x * 128;

    wmma::fragment<wmma::accumulator, 16, 16, 16, float> acc[4][2];
    #pragma unroll
    for (int i = 0; i < 4; i++)
        #pragma unroll
        for (int j = 0; j < 2; j++) wmma::fill_fragment(acc[i][j], 0.0f);

    int ar = tid >> 3;
    int ac = (tid & 7) * 4;
    int br = tid >> 6;
    int bc = (tid & 63) * 2;

    for (int k0 = 0; k0 < K; k0 += 32) {
        #pragma unroll
        for (int p = 0; p < 4; p++) {
            int r = ar + p * 32;
            int gr = row0 + r;
            float4 v = make_float4(0.f, 0.f, 0.f, 0.f);
            if (gr < M) v = *(const float4*)(A + (size_t)gr * K + k0 + ac);
            __nv_bfloat16 hx = __float2bfloat16(v.x);
            __nv_bfloat16 hy = __float2bfloat16(v.y);
            __nv_bfloat16 hz = __float2bfloat16(v.z);
            __nv_bfloat16 hw = __float2bfloat16(v.w);
            AsH[r][ac+0] = hx; AsL[r][ac+0] = __float2bfloat16(v.x - __bfloat162float(hx));
            AsH[r][ac+1] = hy; AsL[r][ac+1] = __float2bfloat16(v.y - __bfloat162float(hy));
            AsH[r][ac+2] = hz; AsL[r][ac+2] = __float2bfloat16(v.z - __bfloat162float(hz));
            AsH[r][ac+3] = hw; AsL[r][ac+3] = __float2bfloat16(v.w - __bfloat162float(hw));
        }
        #pragma unroll
        for (int p = 0; p < 8; p++) {
            int r = br + p * 4;
            float2 v = *(const float2*)(B + (size_t)(k0 + r) * 128 + bc);
            __nv_bfloat16 hx = __float2bfloat16(v.x);
            __nv_bfloat16 hy = __float2bfloat16(v.y);
            BsH[r][bc+0] = hx; BsL[r][bc+0] = __float2bfloat16(v.x - __bfloat162float(hx));
            BsH[r][bc+1] = hy; BsL[r][bc+1] = __float2bfloat16(v.y - __bfloat162float(hy));
        }
        __syncthreads();

        #pragma unroll
        for (int kk = 0; kk < 32; kk += 16) {
            wmma::fragment<wmma::matrix_b, 16, 16, 16, __nv_bfloat16, wmma::row_major> bh[2], bl[2];
            #pragma unroll
            for (int j = 0; j < 2; j++) {
                wmma::load_matrix_sync(bh[j], &BsH[kk][warpN * 32 + j * 16], BSTR);
                wmma::load_matrix_sync(bl[j], &BsL[kk][warpN * 32 + j * 16], BSTR);
            }
            #pragma unroll
            for (int i = 0; i < 4; i++) {
                wmma::fragment<wmma::matrix_a, 16, 16, 16, __nv_bfloat16, wmma::row_major> ah, al;
                wmma::load_matrix_sync(ah, &AsH[warpM * 64 + i * 16][kk], ASTR);
                wmma::load_matrix_sync(al, &AsL[warpM * 64 + i * 16][kk], ASTR);
                #pragma unroll
                for (int j = 0; j < 2; j++) {
                    wmma::mma_sync(acc[i][j], al, bh[j], acc[i][j]);
                    wmma::mma_sync(acc[i][j], ah, bl[j], acc[i][j]);
                    wmma::mma_sync(acc[i][j], ah, bh[j], acc[i][j]);
                }
            }
        }
        __syncthreads();
    }

    if (selHC < 0) {
        float* C = pick(selC);
        #pragma unroll
        for (int i = 0; i < 4; i++)
            #pragma unroll
            for (int j = 0; j < 2; j++) {
                float* cp = C + (size_t)(row0 + warpM * 64 + i * 16) * 128 + warpN * 32 + j * 16;
                wmma::store_matrix_sync(cp, acc[i][j], 128, wmma::mem_row_major);
            }
    } else {
        // fp16 epilogue: stage 16x16 fp32 patch per warp in (reused) smem, pack half2.
        // STG_LD=20 keeps every stage row 16B-aligned (wmma requirement);
        // 8 warps x 16x20 floats = 10240 B = exactly sizeof(AsH).
        __half* Ch = pickH(selHC);
        float* stage = ((float*)AsH) + wid * (16 * STG_LD);
        #pragma unroll
        for (int i = 0; i < 4; i++)
            #pragma unroll
            for (int j = 0; j < 2; j++) {
                wmma::store_matrix_sync(stage, acc[i][j], STG_LD, wmma::mem_row_major);
                __syncwarp();
                int gr0 = row0 + warpM * 64 + i * 16;
                int gc0 = warpN * 32 + j * 16;
                #pragma unroll
                for (int q = 0; q < 4; q++) {
                    int idx = lane * 4 + q;          // 0..127 half2 slots (16x16 patch)
                    int rr = idx >> 3;
                    int cc = (idx & 7) * 2;
                    float2 v = make_float2(stage[rr * STG_LD + cc], stage[rr * STG_LD + cc + 1]);
                    *(__half2*)(Ch + (size_t)(gr0 + rr) * 128 + gc0 + cc) = __float22half2_rn(v);
                }
                __syncwarp();
            }
    }
}

// ---------------- fused CSR gather (fp16 h) + selfloop + bias (+res) + BN + ReLU
// h rows are fp16 (256B/row). Accumulation fp32. selOut<0 => skip row store.
__global__ __launch_bounds__(256)
void k_gather_ep(int selHin, int selOut,
                 const float* __restrict__ bvec,
                 const float* __restrict__ g, const float* __restrict__ be,
                 const float* __restrict__ m, const float* __restrict__ v,
                 int selRes, const float* __restrict__ w3,
                 int node_base, int node_end) {
    int warp = node_base + ((blockIdx.x * blockDim.x + threadIdx.x) >> 5);
    if (warp >= node_end) return;
    int lane = threadIdx.x & 31;
    const __half* h = pickH(selHin);

    float d = g_dis[warp];
    float d2 = d * d;
    uint2 pv = *(const uint2*)(h + (size_t)warp * 128 + lane * 4);
    float2 p01 = __half22float2(*(__half2*)&pv.x);
    float2 p23 = __half22float2(*(__half2*)&pv.y);
    float4 a;
    a.x = p01.x * d2; a.y = p01.y * d2; a.z = p23.x * d2; a.w = p23.y * d2;

    int beg = __ldg(&g_rowptr[warp]), end = __ldg(&g_rowptr[warp + 1]);
    int k = beg;
    for (; k + 3 < end; k += 4) {
        int   ri[4]; float wi[4];
        #pragma unroll
        for (int u = 0; u < 4; u++) { ri[u] = __ldg(&g_srcs[k + u]); wi[u] = __ldg(&g_wS[k + u]); }
        uint2 hv[4];
        #pragma unroll
        for (int u = 0; u < 4; u++)
            hv[u] = *(const uint2*)(h + (size_t)ri[u] * 128 + lane * 4);
        #pragma unroll
        for (int u = 0; u < 4; u++) {
            float2 f01 = __half22float2(*(__half2*)&hv[u].x);
            float2 f23 = __half22float2(*(__half2*)&hv[u].y);
            a.x += f01.x * wi[u];
            a.y += f01.y * wi[u];
            a.z += f23.x * wi[u];
            a.w += f23.y * wi[u];
        }
    }
    for (; k < end; k++) {
        int   r0 = __ldg(&g_srcs[k]);
        float w0 = __ldg(&g_wS[k]);
        uint2 hv = *(const uint2*)(h + (size_t)r0 * 128 + lane * 4);
        float2 f01 = __half22float2(*(__half2*)&hv.x);
        float2 f23 = __half22float2(*(__half2*)&hv.y);
        a.x += f01.x * w0; a.y += f01.y * w0; a.z += f23.x * w0; a.w += f23.y * w0;
    }

    int j4 = lane * 4;
    float4 bv = *(const float4*)(bvec + j4);
    a.x += bv.x; a.y += bv.y; a.z += bv.z; a.w += bv.w;
    if (selRes >= 0) {
        float4 rr = *(const float4*)(pick(selRes) + (size_t)warp * 128 + j4);
        a.x += rr.x; a.y += rr.y; a.z += rr.z; a.w += rr.w;
    }
    float4 gv = *(const float4*)(g + j4);
    float4 vv = *(const float4*)(v + j4);
    float4 mv = *(const float4*)(m + j4);
    float4 bb = *(const float4*)(be + j4);
    float4 o;
    o.x = fmaxf((a.x - mv.x) * (gv.x * rsqrtf(vv.x + 1e-5f)) + bb.x, 0.f);
    o.y = fmaxf((a.y - mv.y) * (gv.y * rsqrtf(vv.y + 1e-5f)) + bb.y, 0.f);
    o.z = fmaxf((a.z - mv.z) * (gv.z * rsqrtf(vv.z + 1e-5f)) + bb.z, 0.f);
    o.w = fmaxf((a.w - mv.w) * (gv.w * rsqrtf(vv.w + 1e-5f)) + bb.w, 0.f);
    if (selOut >= 0)
        *(float4*)(pick(selOut) + (size_t)warp * 128 + j4) = o;

    if (w3) {   // fused GEMV: s = o . w3
        float4 wv = ((const float4*)w3)[lane];
        float s = o.x * wv.x + o.y * wv.y + o.z * wv.z + o.w * wv.w;
        #pragma unroll
        for (int off = 16; off > 0; off >>= 1) s += __shfl_down_sync(0xffffffffu, s, off);
        if (lane == 0) g_s[warp] = s;
    }
}

// ---------------- layer 3: warp-per-node scalar CSR gather -------------------
__global__ __launch_bounds__(256)
void k_out(const float* __restrict__ b3, float* __restrict__ out, int n) {
    int warp = (blockIdx.x * blockDim.x + threadIdx.x) >> 5;
    if (warp >= n) return;
    int lane = threadIdx.x & 31;
    int beg = __ldg(&g_rowptr[warp]), end = __ldg(&g_rowptr[warp + 1]);
    float acc = 0.0f;
    for (int k = beg + lane; k < end; k += 32)
        acc += g_s[__ldg(&g_srcs[k])] * __ldg(&g_wS[k]);
    #pragma unroll
    for (int off = 16; off > 0; off >>= 1) acc += __shfl_down_sync(0xffffffffu, acc, off);
    if (lane == 0) {
        float d = g_dis[warp];
        out[warp] = b3[0] + g_s[warp] * d * d + acc;
    }
}

// ---------------- launch ----------------------------------------------------
extern "C" void kernel_launch(void* const* d_in, const int* in_sizes, int n_in,
                              void* d_out, int out_size) {
    const float* x    = (const float*)d_in[0];
    const int*   ei   = (const int*)d_in[1];     // int32 (JAX x64 disabled)
    const float* ew   = (const float*)d_in[2];
    const float* W1   = (const float*)d_in[3];
    const float* b1   = (const float*)d_in[4];
    const float* W2   = (const float*)d_in[5];
    const float* b2   = (const float*)d_in[6];
    const float* W3   = (const float*)d_in[7];
    const float* b3   = (const float*)d_in[8];
    const float* Wres = (const float*)d_in[9];
    const float* g1   = (const float*)d_in[10];
    const float* be1  = (const float*)d_in[11];
    const float* m1   = (const float*)d_in[12];
    const float* v1   = (const float*)d_in[13];
    const float* g2   = (const float*)d_in[14];
    const float* be2  = (const float*)d_in[15];
    const float* m2   = (const float*)d_in[16];
    const float* v2   = (const float*)d_in[17];
    float* out = (float*)d_out;
    (void)n_in;

    const int N  = out_size;          // 100000
    const int E  = in_sizes[1] / 2;   // 1600000
    const int K1 = in_sizes[0] / N;   // 256

    const int T = 256;
    int nb_N    = (N + T - 1) / T;
    int nb_E    = (E + T - 1) / T;
    int nb_M    = (N + 127) / 128;
    int nb_warp = (N * 32 + T - 1) / T;

    const int H0 = NHALF;             // pipeline halves
    const int H1 = N - H0;
    int nb_h0 = (H0 * 32 + T - 1) / T;
    int nb_h1 = (H1 * 32 + T - 1) / T;
    int nb_M0 = (H0 + 127) / 128;
    int nb_M1 = (H1 + 127) / 128;

    static cudaStream_t s_csr = nullptr, s_g1 = nullptr, s_gr = nullptr;
    static cudaEvent_t  e_fork = nullptr, e_csr = nullptr, e_g1 = nullptr, e_gr = nullptr;
    static cudaEvent_t  e_h0 = nullptr, e_h1 = nullptr;
    if (!s_csr) {
        cudaStreamCreateWithFlags(&s_csr, cudaStreamNonBlocking);
        cudaStreamCreateWithFlags(&s_g1,  cudaStreamNonBlocking);
        cudaStreamCreateWithFlags(&s_gr,  cudaStreamNonBlocking);
        cudaEventCreateWithFlags(&e_fork, cudaEventDisableTiming);
        cudaEventCreateWithFlags(&e_csr,  cudaEventDisableTiming);
        cudaEventCreateWithFlags(&e_g1,   cudaEventDisableTiming);
        cudaEventCreateWithFlags(&e_gr,   cudaEventDisableTiming);
        cudaEventCreateWithFlags(&e_h0,   cudaEventDisableTiming);
        cudaEventCreateWithFlags(&e_h1,   cudaEventDisableTiming);
    }

    // fork
    cudaEventRecord(e_fork, 0);
    cudaStreamWaitEvent(s_csr, e_fork, 0);
    cudaStreamWaitEvent(s_g1,  e_fork, 0);

    // --- CSR build + normalization (stream s_csr) ---
    k_init<<<nb_N, T, 0, s_csr>>>(N);
    k_edge_count<<<nb_E, T, 0, s_csr>>>(ei, ew, E);
    k_scan1<<<SCAN_NB, SCAN_B, 0, s_csr>>>(N);
    k_scan2<<<1, SCAN_B, 0, s_csr>>>(SCAN_NB);
    k_scan3<<<nb_N, T, 0, s_csr>>>(N, E);
    k_fillcsr<<<nb_E, T, 0, s_csr>>>(ei, ew, E);
    cudaEventRecord(e_csr, s_csr);

    // --- layer 1: W1-GEMM at the head, fp16 output to g_hA ---
    gemm_bf16x3<<<nb_M, T, 0, s_g1>>>(x, -1, W1, -1, 0, N, K1, 0);
    cudaEventRecord(e_g1, s_g1);

    // Wres-GEMM (fp32 output to SEL_R) after W1; overlaps gather1+GEMM2 region.
    cudaStreamWaitEvent(s_gr, e_g1, 0);
    gemm_bf16x3<<<nb_M, T, 0, s_gr>>>(x, -1, Wres, SEL_R, -1, N, K1, 0);
    cudaEventRecord(e_gr, s_gr);

    // join CSR + GEMM-W1 before gather1
    cudaStreamWaitEvent(0, e_csr, 0);
    cudaStreamWaitEvent(0, e_g1, 0);

    // --- pipelined propagate1 / GEMM2 over two node halves ---
    // gather1: g_hA -> SEL_B (fp32); GEMM2: SEL_B -> g_hC (fp16)
    k_gather_ep<<<nb_h0, T>>>(0, SEL_B, b1, g1, be1, m1, v1, -1, nullptr, 0, H0);
    cudaEventRecord(e_h0, 0);

    cudaStreamWaitEvent(s_g1, e_h0, 0);
    k_gather_ep<<<nb_h1, T, 0, s_g1>>>(0, SEL_B, b1, g1, be1, m1, v1, -1, nullptr, H0, N);
    cudaEventRecord(e_h1, s_g1);

    gemm_bf16x3<<<nb_M0, T>>>(nullptr, SEL_B, W2, -1, 1, N, 128, 0);

    cudaStreamWaitEvent(0, e_h1, 0);
    gemm_bf16x3<<<nb_M1, T>>>(nullptr, SEL_B, W2, -1, 1, N, 128, H0);

    // join GEMM-Wres before gather2 (its only consumer)
    cudaStreamWaitEvent(0, e_gr, 0);

    // --- propagate 2: h2 rows dead after s = h2.w3 -> no row store ---
    k_gather_ep<<<nb_warp, T>>>(1, -1, b2, g2, be2, m2, v2, SEL_R, W3, 0, N);

    // --- layer 3: scalar gather ---
    k_out<<<nb_warp, T>>>(b3, out, N);
}

// round 17
// speedup vs baseline: 1.2629x; 1.0077x over previous
#include <cuda_runtime.h>
#include <cuda_bf16.h>
#include <cuda_fp16.h>
#include <mma.h>
#include <math.h>

using namespace nvcuda;

#define NN 100000
#define EE 1600000
#define HH 128
#define NPAD (NN + 128)
#define SCAN_B 512
#define SCAN_NB ((NN + SCAN_B - 1) / SCAN_B)   // 196
#define NHALF 50048                            // pipeline split (multiple of 128)

// ---------------- scratch ----------------------------------------------------
__device__ float4 g_bufB4[(size_t)NPAD * HH / 4];   // h1 (gather1 out, GEMM2 in) fp32
__device__ float4 g_res4 [(size_t)NPAD * HH / 4];   // residual fp32
__device__ __half g_hA[(size_t)NPAD * HH];          // h1_pre fp16 (gather1 in)
__device__ __half g_hC[(size_t)NPAD * HH];          // h2_pre fp16 (gather2 in)
__device__ float  g_dis [NN];
__device__ float  g_deg [NN];
__device__ float  g_s   [NN];
__device__ int    g_cnt [NN];
__device__ int    g_cur [NN];
__device__ int    g_partial[NN];
__device__ int    g_bsum[SCAN_B];
__device__ int    g_rowptr[NN + 1];
__device__ int    g_srcs[EE];
__device__ float  g_wS [EE];

#define SEL_B 1
#define SEL_R 2
__device__ __forceinline__ float* pick(int sel) {
    return sel == SEL_B ? (float*)g_bufB4 : (float*)g_res4;
}
__device__ __forceinline__ __half* pickH(int sel) {
    return sel == 0 ? g_hA : g_hC;
}

// ---------------- exact CSR build --------------------------------------------
__global__ void k_init(int n) {
    int i = blockIdx.x * blockDim.x + threadIdx.x;
    if (i < n) { g_deg[i] = 1.0f; g_cnt[i] = 0; g_cur[i] = 0; }
}

__global__ void k_edge_count(const int* __restrict__ ei,
                             const float* __restrict__ ew, int E) {
    int e = blockIdx.x * blockDim.x + threadIdx.x;
    if (e < E) {
        int c = ei[E + e];
        atomicAdd(&g_deg[c], ew[e]);
        atomicAdd(&g_cnt[c], 1);
    }
}

__global__ void k_scan1(int n) {
    __shared__ int sh[SCAN_B];
    int i = blockIdx.x * SCAN_B + threadIdx.x;
    int v = (i < n) ? g_cnt[i] : 0;
    sh[threadIdx.x] = v;
    __syncthreads();
    for (int o = 1; o < SCAN_B; o <<= 1) {
        int t = (threadIdx.x >= o) ? sh[threadIdx.x - o] : 0;
        __syncthreads();
        sh[threadIdx.x] += t;
        __syncthreads();
    }
    if (i < n) g_partial[i] = sh[threadIdx.x] - v;
    if (threadIdx.x == SCAN_B - 1) g_bsum[blockIdx.x] = sh[threadIdx.x];
}

__global__ void k_scan2(int nb) {
    __shared__ int sh[SCAN_B];
    int v = (threadIdx.x < nb) ? g_bsum[threadIdx.x] : 0;
    sh[threadIdx.x] = v;
    __syncthreads();
    for (int o = 1; o < SCAN_B; o <<= 1) {
        int t = (threadIdx.x >= o) ? sh[threadIdx.x - o] : 0;
        __syncthreads();
        sh[threadIdx.x] += t;
        __syncthreads();
    }
    if (threadIdx.x < nb) g_bsum[threadIdx.x] = sh[threadIdx.x] - v;
}

__global__ void k_scan3(int n, int E) {
    int i = blockIdx.x * blockDim.x + threadIdx.x;
    if (i < n) {
        g_rowptr[i] = g_partial[i] + g_bsum[i / SCAN_B];
        g_dis[i] = rsqrtf(g_deg[i]);
    }
    if (i == 0) g_rowptr[n] = E;
}

__global__ void k_fillcsr(const int* __restrict__ ei,
                          const float* __restrict__ ew, int E) {
    int e = blockIdx.x * blockDim.x + threadIdx.x;
    if (e < E) {
        int r = ei[e];
        int c = ei[E + e];
        int pos = g_rowptr[c] + atomicAdd(&g_cur[c], 1);
        g_srcs[pos] = r;
        g_wS[pos]   = g_dis[r] * ew[e] * g_dis[c];
    }
}

// ---------------- bf16x3 tensor-core GEMM (dual-B capable) -------------------
// blockIdx.x selects (B0, selC0, selHC0) or (B1, selC1, selHC1).
// blockIdx.y is the 128-row tile. Co-resident x-pairs share the A tile via L2.
// selHC >= 0: fp16 output to pickH(selHC); else fp32 to pick(selC).
#define ASTR 40
#define BSTR 136
#define STG_LD 20   // fp32 stage stride (multiple of 4: 16B row alignment)
__global__ __launch_bounds__(256, 2)
void gemm_bf16x3(const float* __restrict__ A_ext, int selA,
                 const float* __restrict__ B0, int selC0, int selHC0,
                 const float* __restrict__ B1, int selC1, int selHC1,
                 int M, int K, int row_base) {
    const float* A = (selA < 0) ? A_ext : pick(selA);
    const float* B  = (blockIdx.x == 0) ? B0 : B1;
    int selC  = (blockIdx.x == 0) ? selC0  : selC1;
    int selHC = (blockIdx.x == 0) ? selHC0 : selHC1;

    __shared__ __nv_bfloat16 AsH[128][ASTR], AsL[128][ASTR];
    __shared__ __nv_bfloat16 BsH[32][BSTR],  BsL[32][BSTR];

    int tid = threadIdx.x;
    int wid = tid >> 5;
    int lane = tid & 31;
    int warpM = wid >> 2;
    int warpN = wid & 3;
    int row0 = row_base + blockIdx.y * 128;

    wmma::fragment<wmma::accumulator, 16, 16, 16, float> acc[4][2];
    #pragma unroll
    for (int i = 0; i < 4; i++)
        #pragma unroll
        for (int j = 0; j < 2; j++) wmma::fill_fragment(acc[i][j], 0.0f);

    int ar = tid >> 3;
    int ac = (tid & 7) * 4;
    int br = tid >> 6;
    int bc = (tid & 63) * 2;

    for (int k0 = 0; k0 < K; k0 += 32) {
        #pragma unroll
        for (int p = 0; p < 4; p++) {
            int r = ar + p * 32;
            int gr = row0 + r;
            float4 v = make_float4(0.f, 0.f, 0.f, 0.f);
            if (gr < M) v = *(const float4*)(A + (size_t)gr * K + k0 + ac);
            __nv_bfloat16 hx = __float2bfloat16(v.x);
            __nv_bfloat16 hy = __float2bfloat16(v.y);
            __nv_bfloat16 hz = __float2bfloat16(v.z);
            __nv_bfloat16 hw = __float2bfloat16(v.w);
            AsH[r][ac+0] = hx; AsL[r][ac+0] = __float2bfloat16(v.x - __bfloat162float(hx));
            AsH[r][ac+1] = hy; AsL[r][ac+1] = __float2bfloat16(v.y - __bfloat162float(hy));
            AsH[r][ac+2] = hz; AsL[r][ac+2] = __float2bfloat16(v.z - __bfloat162float(hz));
            AsH[r][ac+3] = hw; AsL[r][ac+3] = __float2bfloat16(v.w - __bfloat162float(hw));
        }
        #pragma unroll
        for (int p = 0; p < 8; p++) {
            int r = br + p * 4;
            float2 v = *(const float2*)(B + (size_t)(k0 + r) * 128 + bc);
            __nv_bfloat16 hx = __float2bfloat16(v.x);
            __nv_bfloat16 hy = __float2bfloat16(v.y);
            BsH[r][bc+0] = hx; BsL[r][bc+0] = __float2bfloat16(v.x - __bfloat162float(hx));
            BsH[r][bc+1] = hy; BsL[r][bc+1] = __float2bfloat16(v.y - __bfloat162float(hy));
        }
        __syncthreads();

        #pragma unroll
        for (int kk = 0; kk < 32; kk += 16) {
            wmma::fragment<wmma::matrix_b, 16, 16, 16, __nv_bfloat16, wmma::row_major> bh[2], bl[2];
            #pragma unroll
            for (int j = 0; j < 2; j++) {
                wmma::load_matrix_sync(bh[j], &BsH[kk][warpN * 32 + j * 16], BSTR);
                wmma::load_matrix_sync(bl[j], &BsL[kk][warpN * 32 + j * 16], BSTR);
            }
            #pragma unroll
            for (int i = 0; i < 4; i++) {
                wmma::fragment<wmma::matrix_a, 16, 16, 16, __nv_bfloat16, wmma::row_major> ah, al;
                wmma::load_matrix_sync(ah, &AsH[warpM * 64 + i * 16][kk], ASTR);
                wmma::load_matrix_sync(al, &AsL[warpM * 64 + i * 16][kk], ASTR);
                #pragma unroll
                for (int j = 0; j < 2; j++) {
                    wmma::mma_sync(acc[i][j], al, bh[j], acc[i][j]);
                    wmma::mma_sync(acc[i][j], ah, bl[j], acc[i][j]);
                    wmma::mma_sync(acc[i][j], ah, bh[j], acc[i][j]);
                }
            }
        }
        __syncthreads();
    }

    if (selHC < 0) {
        float* C = pick(selC);
        #pragma unroll
        for (int i = 0; i < 4; i++)
            #pragma unroll
            for (int j = 0; j < 2; j++) {
                float* cp = C + (size_t)(row0 + warpM * 64 + i * 16) * 128 + warpN * 32 + j * 16;
                wmma::store_matrix_sync(cp, acc[i][j], 128, wmma::mem_row_major);
            }
    } else {
        // fp16 epilogue: per-warp 16x16 fp32 stage (STG_LD=20 keeps 16B alignment)
        __half* Ch = pickH(selHC);
        float* stage = ((float*)AsH) + wid * (16 * STG_LD);
        #pragma unroll
        for (int i = 0; i < 4; i++)
            #pragma unroll
            for (int j = 0; j < 2; j++) {
                wmma::store_matrix_sync(stage, acc[i][j], STG_LD, wmma::mem_row_major);
                __syncwarp();
                int gr0 = row0 + warpM * 64 + i * 16;
                int gc0 = warpN * 32 + j * 16;
                #pragma unroll
                for (int q = 0; q < 4; q++) {
                    int idx = lane * 4 + q;
                    int rr = idx >> 3;
                    int cc = (idx & 7) * 2;
                    float2 v = make_float2(stage[rr * STG_LD + cc], stage[rr * STG_LD + cc + 1]);
                    *(__half2*)(Ch + (size_t)(gr0 + rr) * 128 + gc0 + cc) = __float22half2_rn(v);
                }
                __syncwarp();
            }
    }
}

// ---------------- fused CSR gather (fp16 h) + selfloop + bias (+res) + BN + ReLU
__global__ __launch_bounds__(256)
void k_gather_ep(int selHin, int selOut,
                 const float* __restrict__ bvec,
                 const float* __restrict__ g, const float* __restrict__ be,
                 const float* __restrict__ m, const float* __restrict__ v,
                 int selRes, const float* __restrict__ w3,
                 int node_base, int node_end) {
    int warp = node_base + ((blockIdx.x * blockDim.x + threadIdx.x) >> 5);
    if (warp >= node_end) return;
    int lane = threadIdx.x & 31;
    const __half* h = pickH(selHin);

    float d = g_dis[warp];
    float d2 = d * d;
    uint2 pv = *(const uint2*)(h + (size_t)warp * 128 + lane * 4);
    float2 p01 = __half22float2(*(__half2*)&pv.x);
    float2 p23 = __half22float2(*(__half2*)&pv.y);
    float4 a;
    a.x = p01.x * d2; a.y = p01.y * d2; a.z = p23.x * d2; a.w = p23.y * d2;

    int beg = __ldg(&g_rowptr[warp]), end = __ldg(&g_rowptr[warp + 1]);
    int k = beg;
    for (; k + 3 < end; k += 4) {
        int   ri[4]; float wi[4];
        #pragma unroll
        for (int u = 0; u < 4; u++) { ri[u] = __ldg(&g_srcs[k + u]); wi[u] = __ldg(&g_wS[k + u]); }
        uint2 hv[4];
        #pragma unroll
        for (int u = 0; u < 4; u++)
            hv[u] = *(const uint2*)(h + (size_t)ri[u] * 128 + lane * 4);
        #pragma unroll
        for (int u = 0; u < 4; u++) {
            float2 f01 = __half22float2(*(__half2*)&hv[u].x);
            float2 f23 = __half22float2(*(__half2*)&hv[u].y);
            a.x += f01.x * wi[u];
            a.y += f01.y * wi[u];
            a.z += f23.x * wi[u];
            a.w += f23.y * wi[u];
        }
    }
    for (; k < end; k++) {
        int   r0 = __ldg(&g_srcs[k]);
        float w0 = __ldg(&g_wS[k]);
        uint2 hv = *(const uint2*)(h + (size_t)r0 * 128 + lane * 4);
        float2 f01 = __half22float2(*(__half2*)&hv.x);
        float2 f23 = __half22float2(*(__half2*)&hv.y);
        a.x += f01.x * w0; a.y += f01.y * w0; a.z += f23.x * w0; a.w += f23.y * w0;
    }

    int j4 = lane * 4;
    float4 bv = *(const float4*)(bvec + j4);
    a.x += bv.x; a.y += bv.y; a.z += bv.z; a.w += bv.w;
    if (selRes >= 0) {
        float4 rr = *(const float4*)(pick(selRes) + (size_t)warp * 128 + j4);
        a.x += rr.x; a.y += rr.y; a.z += rr.z; a.w += rr.w;
    }
    float4 gv = *(const float4*)(g + j4);
    float4 vv = *(const float4*)(v + j4);
    float4 mv = *(const float4*)(m + j4);
    float4 bb = *(const float4*)(be + j4);
    float4 o;
    o.x = fmaxf((a.x - mv.x) * (gv.x * rsqrtf(vv.x + 1e-5f)) + bb.x, 0.f);
    o.y = fmaxf((a.y - mv.y) * (gv.y * rsqrtf(vv.y + 1e-5f)) + bb.y, 0.f);
    o.z = fmaxf((a.z - mv.z) * (gv.z * rsqrtf(vv.z + 1e-5f)) + bb.z, 0.f);
    o.w = fmaxf((a.w - mv.w) * (gv.w * rsqrtf(vv.w + 1e-5f)) + bb.w, 0.f);
    if (selOut >= 0)
        *(float4*)(pick(selOut) + (size_t)warp * 128 + j4) = o;

    if (w3) {   // fused GEMV: s = o . w3
        float4 wv = ((const float4*)w3)[lane];
        float s = o.x * wv.x + o.y * wv.y + o.z * wv.z + o.w * wv.w;
        #pragma unroll
        for (int off = 16; off > 0; off >>= 1) s += __shfl_down_sync(0xffffffffu, s, off);
        if (lane == 0) g_s[warp] = s;
    }
}

// ---------------- layer 3: warp-per-node scalar CSR gather -------------------
__global__ __launch_bounds__(256)
void k_out(const float* __restrict__ b3, float* __restrict__ out, int n) {
    int warp = (blockIdx.x * blockDim.x + threadIdx.x) >> 5;
    if (warp >= n) return;
    int lane = threadIdx.x & 31;
    int beg = __ldg(&g_rowptr[warp]), end = __ldg(&g_rowptr[warp + 1]);
    float acc = 0.0f;
    for (int k = beg + lane; k < end; k += 32)
        acc += g_s[__ldg(&g_srcs[k])] * __ldg(&g_wS[k]);
    #pragma unroll
    for (int off = 16; off > 0; off >>= 1) acc += __shfl_down_sync(0xffffffffu, acc, off);
    if (lane == 0) {
        float d = g_dis[warp];
        out[warp] = b3[0] + g_s[warp] * d * d + acc;
    }
}

// ---------------- launch ----------------------------------------------------
extern "C" void kernel_launch(void* const* d_in, const int* in_sizes, int n_in,
                              void* d_out, int out_size) {
    const float* x    = (const float*)d_in[0];
    const int*   ei   = (const int*)d_in[1];     // int32 (JAX x64 disabled)
    const float* ew   = (const float*)d_in[2];
    const float* W1   = (const float*)d_in[3];
    const float* b1   = (const float*)d_in[4];
    const float* W2   = (const float*)d_in[5];
    const float* b2   = (const float*)d_in[6];
    const float* W3   = (const float*)d_in[7];
    const float* b3   = (const float*)d_in[8];
    const float* Wres = (const float*)d_in[9];
    const float* g1   = (const float*)d_in[10];
    const float* be1  = (const float*)d_in[11];
    const float* m1   = (const float*)d_in[12];
    const float* v1   = (const float*)d_in[13];
    const float* g2   = (const float*)d_in[14];
    const float* be2  = (const float*)d_in[15];
    const float* m2   = (const float*)d_in[16];
    const float* v2   = (const float*)d_in[17];
    float* out = (float*)d_out;
    (void)n_in;

    const int N  = out_size;          // 100000
    const int E  = in_sizes[1] / 2;   // 1600000
    const int K1 = in_sizes[0] / N;   // 256

    const int T = 256;
    int nb_N    = (N + T - 1) / T;
    int nb_E    = (E + T - 1) / T;
    int nb_M    = (N + 127) / 128;
    int nb_warp = (N * 32 + T - 1) / T;

    const int H0 = NHALF;             // pipeline halves
    const int H1 = N - H0;
    int nb_h0 = (H0 * 32 + T - 1) / T;
    int nb_h1 = (H1 * 32 + T - 1) / T;
    int nb_M0 = (H0 + 127) / 128;
    int nb_M1 = (H1 + 127) / 128;

    static cudaStream_t s_csr = nullptr, s_g1 = nullptr;
    static cudaEvent_t  e_fork = nullptr, e_csr = nullptr, e_g1 = nullptr;
    static cudaEvent_t  e_h0 = nullptr, e_h1 = nullptr;
    if (!s_csr) {
        cudaStreamCreateWithFlags(&s_csr, cudaStreamNonBlocking);
        cudaStreamCreateWithFlags(&s_g1,  cudaStreamNonBlocking);
        cudaEventCreateWithFlags(&e_fork, cudaEventDisableTiming);
        cudaEventCreateWithFlags(&e_csr,  cudaEventDisableTiming);
        cudaEventCreateWithFlags(&e_g1,   cudaEventDisableTiming);
        cudaEventCreateWithFlags(&e_h0,   cudaEventDisableTiming);
        cudaEventCreateWithFlags(&e_h1,   cudaEventDisableTiming);
    }

    // fork
    cudaEventRecord(e_fork, 0);
    cudaStreamWaitEvent(s_csr, e_fork, 0);
    cudaStreamWaitEvent(s_g1,  e_fork, 0);

    // --- CSR build + normalization (stream s_csr) ---
    k_init<<<nb_N, T, 0, s_csr>>>(N);
    k_edge_count<<<nb_E, T, 0, s_csr>>>(ei, ew, E);
    k_scan1<<<SCAN_NB, SCAN_B, 0, s_csr>>>(N);
    k_scan2<<<1, SCAN_B, 0, s_csr>>>(SCAN_NB);
    k_scan3<<<nb_N, T, 0, s_csr>>>(N, E);
    k_fillcsr<<<nb_E, T, 0, s_csr>>>(ei, ew, E);
    cudaEventRecord(e_csr, s_csr);

    // --- layer 1: dual GEMM [h1_pre | res] = x @ [W1 | Wres], one launch ---
    // grid (2, nb_M): x-pairs co-resident -> shared A tiles via L2.
    // side 0: W1 -> fp16 g_hA ; side 1: Wres -> fp32 SEL_R
    gemm_bf16x3<<<dim3(2, nb_M), T, 0, s_g1>>>(x, -1,
                                               W1,   -1,    0,
                                               Wres, SEL_R, -1,
                                               N, K1, 0);
    cudaEventRecord(e_g1, s_g1);

    // join CSR + dual GEMM before gather1
    cudaStreamWaitEvent(0, e_csr, 0);
    cudaStreamWaitEvent(0, e_g1, 0);

    // --- pipelined propagate1 / GEMM2 over two node halves ---
    // gather1: g_hA -> SEL_B (fp32); GEMM2: SEL_B -> g_hC (fp16)
    k_gather_ep<<<nb_h0, T>>>(0, SEL_B, b1, g1, be1, m1, v1, -1, nullptr, 0, H0);
    cudaEventRecord(e_h0, 0);

    cudaStreamWaitEvent(s_g1, e_h0, 0);
    k_gather_ep<<<nb_h1, T, 0, s_g1>>>(0, SEL_B, b1, g1, be1, m1, v1, -1, nullptr, H0, N);
    cudaEventRecord(e_h1, s_g1);

    gemm_bf16x3<<<dim3(1, nb_M0), T>>>(nullptr, SEL_B,
                                       W2, -1, 1,
                                       nullptr, -1, 1,
                                       N, 128, 0);

    cudaStreamWaitEvent(0, e_h1, 0);
    gemm_bf16x3<<<dim3(1, nb_M1), T>>>(nullptr, SEL_B,
                                       W2, -1, 1,
                                       nullptr, -1, 1,
                                       N, 128, H0);

    // --- propagate 2: residual fused; h2 rows dead after s = h2.w3 ---
    k_gather_ep<<<nb_warp, T>>>(1, -1, b2, g2, be2, m2, v2, SEL_R, W3, 0, N);

    // --- layer 3: scalar gather ---
    k_out<<<nb_warp, T>>>(b3, out, N);
}